// round 13
// baseline (speedup 1.0000x reference)
#include <cuda_runtime.h>
#include <cuda_bf16.h>
#include <math.h>
#include <stdint.h>

#define N_TOK   4096
#define DIM     1024
#define HEADS   8
#define DHEAD   64
#define DINNER  512
#define QKV_N   1536

// Scratch (allocation-free rule: __device__ globals)
__device__ __nv_bfloat16 g_xh[(size_t)N_TOK * DIM],     g_xl[(size_t)N_TOK * DIM];
__device__ __nv_bfloat16 g_wqh[(size_t)DIM * QKV_N],    g_wql[(size_t)DIM * QKV_N];
__device__ __nv_bfloat16 g_woh[(size_t)DINNER * DIM],   g_wol[(size_t)DINNER * DIM];
__device__ __nv_bfloat16 g_qkvh[(size_t)N_TOK * QKV_N], g_qkvl[(size_t)N_TOK * QKV_N];
__device__ __nv_bfloat16 g_aoh[(size_t)N_TOK * DINNER], g_aol[(size_t)N_TOK * DINNER];
// split-K attention partials (zero-initialized; empty chunks never write ->
// merge's l2==0 branch treats them as absent)
__device__ float g_opart[2][N_TOK][DINNER];
__device__ float g_ml[2][HEADS][N_TOK][2];

// ---------------------------------------------------------------------------
// Helpers
// ---------------------------------------------------------------------------
__device__ __forceinline__ void mma16816(float* c,
    uint32_t a0, uint32_t a1, uint32_t a2, uint32_t a3,
    uint32_t b0, uint32_t b1) {
    asm volatile(
        "mma.sync.aligned.m16n8k16.row.col.f32.bf16.bf16.f32 "
        "{%0,%1,%2,%3}, {%4,%5,%6,%7}, {%8,%9}, {%0,%1,%2,%3};"
        : "+f"(c[0]), "+f"(c[1]), "+f"(c[2]), "+f"(c[3])
        : "r"(a0), "r"(a1), "r"(a2), "r"(a3), "r"(b0), "r"(b1));
}
__device__ __forceinline__ void ldsm4(uint32_t& r0, uint32_t& r1,
                                      uint32_t& r2, uint32_t& r3, const void* p) {
    uint32_t a = (uint32_t)__cvta_generic_to_shared(p);
    asm volatile("ldmatrix.sync.aligned.m8n8.x4.shared.b16 {%0,%1,%2,%3}, [%4];"
                 : "=r"(r0), "=r"(r1), "=r"(r2), "=r"(r3) : "r"(a));
}
__device__ __forceinline__ void ldsm4t(uint32_t& r0, uint32_t& r1,
                                       uint32_t& r2, uint32_t& r3, const void* p) {
    uint32_t a = (uint32_t)__cvta_generic_to_shared(p);
    asm volatile("ldmatrix.sync.aligned.m8n8.x4.trans.shared.b16 {%0,%1,%2,%3}, [%4];"
                 : "=r"(r0), "=r"(r1), "=r"(r2), "=r"(r3) : "r"(a));
}
__device__ __forceinline__ void split2(float v0, float v1,
                                       uint32_t& hi, uint32_t& lo) {
    __nv_bfloat16 h0 = __float2bfloat16_rn(v0);
    __nv_bfloat16 h1 = __float2bfloat16_rn(v1);
    __nv_bfloat16 l0 = __float2bfloat16_rn(v0 - __bfloat162float(h0));
    __nv_bfloat16 l1 = __float2bfloat16_rn(v1 - __bfloat162float(h1));
    __nv_bfloat162 hp; hp.x = h0; hp.y = h1;
    __nv_bfloat162 lp; lp.x = l0; lp.y = l1;
    hi = *(uint32_t*)&hp;
    lo = *(uint32_t*)&lp;
}
__device__ __forceinline__ void cp16(uint32_t d, const void* s) {
    asm volatile("cp.async.cg.shared.global [%0], [%1], 16;" :: "r"(d), "l"(s));
}
__device__ __forceinline__ void cpcommit() { asm volatile("cp.async.commit_group;" ::: "memory"); }
__device__ __forceinline__ void cpwait0()  { asm volatile("cp.async.wait_group 0;" ::: "memory"); }
__device__ __forceinline__ void cpwait1()  { asm volatile("cp.async.wait_group 1;" ::: "memory"); }

// ---------------------------------------------------------------------------
// Kernel 1: fused rmsnorm + gamma + bf16 hi/lo split of x.
// ---------------------------------------------------------------------------
__global__ __launch_bounds__(256)
void rms_split_x_kernel(const float4* __restrict__ x,
                        const float* __restrict__ gamma) {
    int row = blockIdx.x;
    float4 v = x[(size_t)row * 256 + threadIdx.x];
    float s = v.x * v.x + v.y * v.y + v.z * v.z + v.w * v.w;
    #pragma unroll
    for (int o = 16; o; o >>= 1) s += __shfl_xor_sync(0xffffffffu, s, o);
    __shared__ float ws[8];
    if ((threadIdx.x & 31) == 0) ws[threadIdx.x >> 5] = s;
    __syncthreads();
    float t = 0.f;
    #pragma unroll
    for (int i = 0; i < 8; i++) t += ws[i];
    float sc = 32.0f / fmaxf(sqrtf(t), 1e-12f);

    int col = threadIdx.x * 4;
    float4 gm = *(const float4*)(gamma + col);
    uint32_t h0, l0, h1, l1;
    split2(v.x * sc * gm.x, v.y * sc * gm.y, h0, l0);
    split2(v.z * sc * gm.z, v.w * sc * gm.w, h1, l1);
    size_t o4 = (size_t)row * DIM + col;
    *(uint2*)&g_xh[o4] = make_uint2(h0, h1);
    *(uint2*)&g_xl[o4] = make_uint2(l0, l1);
}

__global__ void split_w_kernel(const float4* __restrict__ w,
                               __nv_bfloat16* __restrict__ hi,
                               __nv_bfloat16* __restrict__ lo) {
    int i = blockIdx.x * 256 + threadIdx.x;
    float4 v = w[i];
    uint32_t h0, l0, h1, l1;
    split2(v.x, v.y, h0, l0);
    split2(v.z, v.w, h1, l1);
    *(uint2*)&hi[(size_t)4 * i] = make_uint2(h0, h1);
    *(uint2*)&lo[(size_t)4 * i] = make_uint2(l0, l1);
}

// ---------------------------------------------------------------------------
// bf16-split HMMA GEMM (R12 version): 128x64 tile, BK=32, cp.async 2-stage,
// ldmatrix.x4 operand fetch, products interleaved (RAW distance 4).
// ---------------------------------------------------------------------------
#define GA_ELE (128 * 40)
#define GB_ELE (32 * 72)
#define GSTAGE_ELE (2 * GA_ELE + 2 * GB_ELE)
#define GEMM_SMEM (2 * GSTAGE_ELE * 2)

template <bool SPLIT_OUT>
__global__ __launch_bounds__(256)
void mma_gemm_kernel(const __nv_bfloat16* __restrict__ Ah,
                     const __nv_bfloat16* __restrict__ Al,
                     const __nv_bfloat16* __restrict__ Bh,
                     const __nv_bfloat16* __restrict__ Bl,
                     float* __restrict__ C,
                     __nv_bfloat16* __restrict__ Ch,
                     __nv_bfloat16* __restrict__ Cl,
                     int M, int N, int K) {
    extern __shared__ __align__(16) __nv_bfloat16 smg[];
    uint32_t smg_u = (uint32_t)__cvta_generic_to_shared(smg);
    int tid = threadIdx.x;
    int wid = tid >> 5, lane = tid & 31;
    int g = lane >> 2, t = lane & 3;
    int wm = wid & 3, wn = wid >> 2;
    int m0 = blockIdx.y * 128, n0 = blockIdx.x * 64;

    int arow = ((lane >> 3) & 1) * 8 + (lane & 7);
    int acol = (lane >> 4) * 8;
    int brow = lane & 15;
    int bcol = (lane >> 4) * 8;

    int a0r = tid >> 2,         a0k = (tid & 3) * 8;
    int a1r = (tid + 256) >> 2, a1k = ((tid + 256) & 3) * 8;
    int lbr = tid >> 3,         lbn = (tid & 7) * 8;

    #define G_LOAD(buf_, k0_) do {                                              \
        uint32_t sb = smg_u + (buf_) * (GSTAGE_ELE * 2);                        \
        cp16(sb + (a0r * 40 + a0k) * 2,                                         \
             Ah + (size_t)(m0 + a0r) * K + (k0_) + a0k);                        \
        cp16(sb + (a1r * 40 + a1k) * 2,                                         \
             Ah + (size_t)(m0 + a1r) * K + (k0_) + a1k);                        \
        cp16(sb + (GA_ELE + a0r * 40 + a0k) * 2,                                \
             Al + (size_t)(m0 + a0r) * K + (k0_) + a0k);                        \
        cp16(sb + (GA_ELE + a1r * 40 + a1k) * 2,                                \
             Al + (size_t)(m0 + a1r) * K + (k0_) + a1k);                        \
        cp16(sb + (2 * GA_ELE + lbr * 72 + lbn) * 2,                            \
             Bh + (size_t)((k0_) + lbr) * N + n0 + lbn);                        \
        cp16(sb + (2 * GA_ELE + GB_ELE + lbr * 72 + lbn) * 2,                   \
             Bl + (size_t)((k0_) + lbr) * N + n0 + lbn);                        \
        cpcommit();                                                             \
    } while (0)

    float c[2][4][4];
    #pragma unroll
    for (int mt = 0; mt < 2; mt++)
        #pragma unroll
        for (int nt = 0; nt < 4; nt++)
            #pragma unroll
            for (int e = 0; e < 4; e++) c[mt][nt][e] = 0.f;

    const int S = K / 32;
    G_LOAD(0, 0);
    for (int s = 0; s < S; s++) {
        if (s + 1 < S) { G_LOAD((s + 1) & 1, (s + 1) * 32); cpwait1(); }
        else           { cpwait0(); }
        __syncthreads();

        const __nv_bfloat16* stg = smg + (s & 1) * GSTAGE_ELE;
        const __nv_bfloat16* As0 = stg;
        const __nv_bfloat16* As1 = stg + GA_ELE;
        const __nv_bfloat16* Bs0 = stg + 2 * GA_ELE;
        const __nv_bfloat16* Bs1 = stg + 2 * GA_ELE + GB_ELE;

        #pragma unroll
        for (int kk = 0; kk < 32; kk += 16) {
            uint32_t ah[2][4], al[2][4];
            #pragma unroll
            for (int mt = 0; mt < 2; mt++) {
                int r = wm * 32 + mt * 16;
                ldsm4(ah[mt][0], ah[mt][1], ah[mt][2], ah[mt][3],
                      &As0[(r + arow) * 40 + kk + acol]);
                ldsm4(al[mt][0], al[mt][1], al[mt][2], al[mt][3],
                      &As1[(r + arow) * 40 + kk + acol]);
            }
            #pragma unroll
            for (int p2 = 0; p2 < 2; p2++) {
                uint32_t bh0, bh1, bh2, bh3, bl0, bl1, bl2, bl3;
                ldsm4t(bh0, bh1, bh2, bh3,
                       &Bs0[(kk + brow) * 72 + wn * 32 + p2 * 16 + bcol]);
                ldsm4t(bl0, bl1, bl2, bl3,
                       &Bs1[(kk + brow) * 72 + wn * 32 + p2 * 16 + bcol]);
                mma16816(c[0][2*p2],   ah[0][0], ah[0][1], ah[0][2], ah[0][3], bh0, bh1);
                mma16816(c[0][2*p2+1], ah[0][0], ah[0][1], ah[0][2], ah[0][3], bh2, bh3);
                mma16816(c[1][2*p2],   ah[1][0], ah[1][1], ah[1][2], ah[1][3], bh0, bh1);
                mma16816(c[1][2*p2+1], ah[1][0], ah[1][1], ah[1][2], ah[1][3], bh2, bh3);
                mma16816(c[0][2*p2],   ah[0][0], ah[0][1], ah[0][2], ah[0][3], bl0, bl1);
                mma16816(c[0][2*p2+1], ah[0][0], ah[0][1], ah[0][2], ah[0][3], bl2, bl3);
                mma16816(c[1][2*p2],   ah[1][0], ah[1][1], ah[1][2], ah[1][3], bl0, bl1);
                mma16816(c[1][2*p2+1], ah[1][0], ah[1][1], ah[1][2], ah[1][3], bl2, bl3);
                mma16816(c[0][2*p2],   al[0][0], al[0][1], al[0][2], al[0][3], bh0, bh1);
                mma16816(c[0][2*p2+1], al[0][0], al[0][1], al[0][2], al[0][3], bh2, bh3);
                mma16816(c[1][2*p2],   al[1][0], al[1][1], al[1][2], al[1][3], bh0, bh1);
                mma16816(c[1][2*p2+1], al[1][0], al[1][1], al[1][2], al[1][3], bh2, bh3);
            }
        }
        __syncthreads();
    }

    #pragma unroll
    for (int mt = 0; mt < 2; mt++) {
        #pragma unroll
        for (int nt = 0; nt < 4; nt++) {
            int rowA = m0 + wm * 32 + mt * 16 + g;
            int col = n0 + wn * 32 + nt * 8 + 2 * t;
            if (SPLIT_OUT) {
                uint32_t hi, lo;
                split2(c[mt][nt][0], c[mt][nt][1], hi, lo);
                *(uint32_t*)&Ch[(size_t)rowA * N + col] = hi;
                *(uint32_t*)&Cl[(size_t)rowA * N + col] = lo;
                split2(c[mt][nt][2], c[mt][nt][3], hi, lo);
                *(uint32_t*)&Ch[(size_t)(rowA + 8) * N + col] = hi;
                *(uint32_t*)&Cl[(size_t)(rowA + 8) * N + col] = lo;
            } else {
                *(float2*)&C[(size_t)rowA * N + col] =
                    make_float2(c[mt][nt][0], c[mt][nt][1]);
                *(float2*)&C[(size_t)(rowA + 8) * N + col] =
                    make_float2(c[mt][nt][2], c[mt][nt][3]);
            }
        }
    }
    #undef G_LOAD
}

// ---------------------------------------------------------------------------
// Flash attention, SPLIT-K over the key range: grid (64, 8, 2).
// chunk 0: kt in [0, ceil(n/2)); chunk 1: [ceil(n/2), n), n = qt+1.
// Each chunk writes UNNORMALIZED fp32 partial O + (m, l); merge kernel
// combines. K/V cp.async double-buffered, ldmatrix.x4, Q frags in regs.
// ---------------------------------------------------------------------------
#define AT_ARR 4608
#define AT_STAGE (4 * AT_ARR)
#define ATT_SMEM (2 * AT_STAGE * 2)

__global__ __launch_bounds__(128)
void mma_attn_kernel(const __nv_bfloat16* __restrict__ qh,
                     const __nv_bfloat16* __restrict__ ql) {
    extern __shared__ __align__(16) __nv_bfloat16 smb[];
    uint32_t smb_u = (uint32_t)__cvta_generic_to_shared(smb);

    int qt = 63 - blockIdx.x;          // heavy tiles first
    int h = blockIdx.y;
    int chunk = blockIdx.z;
    int n = qt + 1;
    int half = (n + 1) >> 1;
    int start = chunk ? half : 0;
    int end   = chunk ? n : half;
    if (start >= end) return;          // empty chunk: scratch stays zero

    int tid = threadIdx.x;
    int wid = tid >> 5, lane = tid & 31;
    int g = lane >> 2, t = lane & 3;
    int r0 = wid * 16;
    int gA = qt * 64 + r0 + g;

    int krow = ((lane >> 4) & 1) * 8 + (lane & 7);
    int kcol = ((lane >> 3) & 1) * 8;
    int vrow = lane & 15;
    int vcol = (lane >> 4) * 8;

    #define LOAD_KV(kt_, buf_) do {                                            \
        uint32_t sbase = smb_u + (buf_) * (AT_STAGE * 2);                      \
        _Pragma("unroll")                                                      \
        for (int j = 0; j < 4; j++) {                                          \
            int p = tid + j * 128;                                             \
            int rr = p >> 3, c8 = (p & 7) * 8;                                 \
            uint32_t dso = rr * 144 + c8 * 2;                                  \
            size_t base = (size_t)((kt_) * 64 + rr) * QKV_N + h * DHEAD + c8;  \
            cp16(sbase + dso,                  qh + base + DINNER);            \
            cp16(sbase + AT_ARR * 2 + dso,     ql + base + DINNER);            \
            cp16(sbase + 2 * AT_ARR * 2 + dso, qh + base + 2 * DINNER);        \
            cp16(sbase + 3 * AT_ARR * 2 + dso, ql + base + 2 * DINNER);        \
        }                                                                      \
        cpcommit();                                                            \
    } while (0)

    uint32_t ahq[4][4], alq[4][4];
    {
        size_t rA = (size_t)gA * QKV_N + h * DHEAD;
        size_t rB = (size_t)(gA + 8) * QKV_N + h * DHEAD;
        #pragma unroll
        for (int d16 = 0; d16 < 4; d16++) {
            int cA = d16 * 16 + 2 * t, cB = d16 * 16 + 8 + 2 * t;
            ahq[d16][0] = *(const uint32_t*)&qh[rA + cA];
            ahq[d16][1] = *(const uint32_t*)&qh[rB + cA];
            ahq[d16][2] = *(const uint32_t*)&qh[rA + cB];
            ahq[d16][3] = *(const uint32_t*)&qh[rB + cB];
            alq[d16][0] = *(const uint32_t*)&ql[rA + cA];
            alq[d16][1] = *(const uint32_t*)&ql[rB + cA];
            alq[d16][2] = *(const uint32_t*)&ql[rA + cB];
            alq[d16][3] = *(const uint32_t*)&ql[rB + cB];
        }
    }

    float o[8][4];
    #pragma unroll
    for (int nt = 0; nt < 8; nt++)
        #pragma unroll
        for (int e = 0; e < 4; e++) o[nt][e] = 0.f;
    float m[2] = {-1e30f, -1e30f}, l[2] = {0.f, 0.f};

    LOAD_KV(start, start & 1);

    for (int kt = start; kt < end; kt++) {
        __syncthreads();
        if (kt + 1 < end) { LOAD_KV(kt + 1, (kt + 1) & 1); cpwait1(); }
        else              { cpwait0(); }
        __syncthreads();

        const __nv_bfloat16* stg = smb + (kt & 1) * AT_STAGE;
        const __nv_bfloat16* Kh = stg;
        const __nv_bfloat16* Kl = stg + AT_ARR;
        const __nv_bfloat16* Vh = stg + 2 * AT_ARR;
        const __nv_bfloat16* Vl = stg + 3 * AT_ARR;

        float sc[8][4];
        #pragma unroll
        for (int nt = 0; nt < 8; nt++)
            #pragma unroll
            for (int e = 0; e < 4; e++) sc[nt][e] = 0.f;

        #pragma unroll
        for (int d16 = 0; d16 < 4; d16++) {
            #pragma unroll
            for (int p2 = 0; p2 < 4; p2++) {
                uint32_t bh0, bh1, bh2, bh3, bl0, bl1, bl2, bl3;
                ldsm4(bh0, bh1, bh2, bh3,
                      &Kh[(p2 * 16 + krow) * 72 + d16 * 16 + kcol]);
                ldsm4(bl0, bl1, bl2, bl3,
                      &Kl[(p2 * 16 + krow) * 72 + d16 * 16 + kcol]);
                mma16816(sc[2*p2],   ahq[d16][0], ahq[d16][1], ahq[d16][2], ahq[d16][3], bh0, bh1);
                mma16816(sc[2*p2+1], ahq[d16][0], ahq[d16][1], ahq[d16][2], ahq[d16][3], bh2, bh3);
                mma16816(sc[2*p2],   ahq[d16][0], ahq[d16][1], ahq[d16][2], ahq[d16][3], bl0, bl1);
                mma16816(sc[2*p2+1], ahq[d16][0], ahq[d16][1], ahq[d16][2], ahq[d16][3], bl2, bl3);
                mma16816(sc[2*p2],   alq[d16][0], alq[d16][1], alq[d16][2], alq[d16][3], bh0, bh1);
                mma16816(sc[2*p2+1], alq[d16][0], alq[d16][1], alq[d16][2], alq[d16][3], bh2, bh3);
            }
        }

        #pragma unroll
        for (int nt = 0; nt < 8; nt++)
            #pragma unroll
            for (int e = 0; e < 4; e++) sc[nt][e] *= 8.f;

        if (kt == qt) {
            #pragma unroll
            for (int nt = 0; nt < 8; nt++) {
                int colb = nt * 8 + 2 * t;
                int rA = r0 + g, rB = r0 + 8 + g;
                if (colb > rA)     sc[nt][0] = -1e30f;
                if (colb + 1 > rA) sc[nt][1] = -1e30f;
                if (colb > rB)     sc[nt][2] = -1e30f;
                if (colb + 1 > rB) sc[nt][3] = -1e30f;
            }
        }

        #pragma unroll
        for (int hf = 0; hf < 2; hf++) {
            float mx = -1e30f;
            #pragma unroll
            for (int nt = 0; nt < 8; nt++) {
                mx = fmaxf(mx, sc[nt][2 * hf]);
                mx = fmaxf(mx, sc[nt][2 * hf + 1]);
            }
            mx = fmaxf(mx, __shfl_xor_sync(0xffffffffu, mx, 1));
            mx = fmaxf(mx, __shfl_xor_sync(0xffffffffu, mx, 2));
            float mnew = fmaxf(m[hf], mx);
            float corr = __expf(m[hf] - mnew);
            m[hf] = mnew;
            float sum = 0.f;
            #pragma unroll
            for (int nt = 0; nt < 8; nt++) {
                float p0 = __expf(sc[nt][2 * hf] - mnew);
                float p1 = __expf(sc[nt][2 * hf + 1] - mnew);
                sc[nt][2 * hf] = p0;
                sc[nt][2 * hf + 1] = p1;
                sum += p0 + p1;
            }
            sum += __shfl_xor_sync(0xffffffffu, sum, 1);
            sum += __shfl_xor_sync(0xffffffffu, sum, 2);
            l[hf] = l[hf] * corr + sum;
            #pragma unroll
            for (int nt = 0; nt < 8; nt++) {
                o[nt][2 * hf] *= corr;
                o[nt][2 * hf + 1] *= corr;
            }
        }

        uint32_t phf[4][4], plf[4][4];
        #pragma unroll
        for (int kk = 0; kk < 4; kk++) {
            split2(sc[2 * kk][0], sc[2 * kk][1], phf[kk][0], plf[kk][0]);
            split2(sc[2 * kk][2], sc[2 * kk][3], phf[kk][1], plf[kk][1]);
            split2(sc[2 * kk + 1][0], sc[2 * kk + 1][1], phf[kk][2], plf[kk][2]);
            split2(sc[2 * kk + 1][2], sc[2 * kk + 1][3], phf[kk][3], plf[kk][3]);
        }

        #pragma unroll
        for (int kk = 0; kk < 4; kk++) {
            #pragma unroll
            for (int p2 = 0; p2 < 4; p2++) {
                uint32_t vh0, vh1, vh2, vh3, vl0, vl1, vl2, vl3;
                ldsm4t(vh0, vh1, vh2, vh3,
                       &Vh[(kk * 16 + vrow) * 72 + p2 * 16 + vcol]);
                ldsm4t(vl0, vl1, vl2, vl3,
                       &Vl[(kk * 16 + vrow) * 72 + p2 * 16 + vcol]);
                mma16816(o[2*p2],   phf[kk][0], phf[kk][1], phf[kk][2], phf[kk][3], vh0, vh1);
                mma16816(o[2*p2+1], phf[kk][0], phf[kk][1], phf[kk][2], phf[kk][3], vh2, vh3);
                mma16816(o[2*p2],   phf[kk][0], phf[kk][1], phf[kk][2], phf[kk][3], vl0, vl1);
                mma16816(o[2*p2+1], phf[kk][0], phf[kk][1], phf[kk][2], phf[kk][3], vl2, vl3);
                mma16816(o[2*p2],   plf[kk][0], plf[kk][1], plf[kk][2], plf[kk][3], vh0, vh1);
                mma16816(o[2*p2+1], plf[kk][0], plf[kk][1], plf[kk][2], plf[kk][3], vh2, vh3);
            }
        }
    }

    // write unnormalized partials
    #pragma unroll
    for (int nt = 0; nt < 8; nt++) {
        int col = h * DHEAD + nt * 8 + 2 * t;
        *(float2*)&g_opart[chunk][gA][col]     = make_float2(o[nt][0], o[nt][1]);
        *(float2*)&g_opart[chunk][gA + 8][col] = make_float2(o[nt][2], o[nt][3]);
    }
    if (t == 0) {
        g_ml[chunk][h][gA][0]     = m[0];
        g_ml[chunk][h][gA][1]     = l[0];
        g_ml[chunk][h][gA + 8][0] = m[1];
        g_ml[chunk][h][gA + 8][1] = l[1];
    }
    #undef LOAD_KV
}

// ---------------------------------------------------------------------------
// Merge the two split-K partials, normalize, emit hi/lo split of ao.
// ---------------------------------------------------------------------------
__global__ __launch_bounds__(256)
void attn_merge_kernel() {
    int row = blockIdx.x;
    int c0 = threadIdx.x * 2;
    int h = c0 >> 6;
    float m1 = g_ml[0][h][row][0], l1 = g_ml[0][h][row][1];
    float m2 = g_ml[1][h][row][0], l2 = g_ml[1][h][row][1];
    float2 o1 = *(const float2*)&g_opart[0][row][c0];
    float r0, r1;
    if (l2 == 0.f) {                       // chunk B absent (scratch untouched)
        float inv = 1.f / l1;
        r0 = o1.x * inv;
        r1 = o1.y * inv;
    } else {
        float2 o2 = *(const float2*)&g_opart[1][row][c0];
        float mm = fmaxf(m1, m2);
        float f1 = __expf(m1 - mm), f2 = __expf(m2 - mm);
        float inv = 1.f / (l1 * f1 + l2 * f2);
        r0 = (o1.x * f1 + o2.x * f2) * inv;
        r1 = (o1.y * f1 + o2.y * f2) * inv;
    }
    uint32_t hi, lo;
    split2(r0, r1, hi, lo);
    size_t idx = (size_t)row * DINNER + c0;
    *(uint32_t*)&g_aoh[idx] = hi;
    *(uint32_t*)&g_aol[idx] = lo;
}

// ---------------------------------------------------------------------------
extern "C" void kernel_launch(void* const* d_in, const int* in_sizes, int n_in,
                              void* d_out, int out_size) {
    const float* x     = (const float*)d_in[0];
    const float* gamma = (const float*)d_in[1];
    const float* w_qkv = (const float*)d_in[2];
    const float* w_out = (const float*)d_in[3];
    float* out = (float*)d_out;

    __nv_bfloat16 *xh, *xl, *wqh, *wql, *woh, *wol, *qkvh, *qkvl, *aoh, *aol;
    cudaGetSymbolAddress((void**)&xh, g_xh);
    cudaGetSymbolAddress((void**)&xl, g_xl);
    cudaGetSymbolAddress((void**)&wqh, g_wqh);
    cudaGetSymbolAddress((void**)&wql, g_wql);
    cudaGetSymbolAddress((void**)&woh, g_woh);
    cudaGetSymbolAddress((void**)&wol, g_wol);
    cudaGetSymbolAddress((void**)&qkvh, g_qkvh);
    cudaGetSymbolAddress((void**)&qkvl, g_qkvl);
    cudaGetSymbolAddress((void**)&aoh, g_aoh);
    cudaGetSymbolAddress((void**)&aol, g_aol);

    cudaFuncSetAttribute(mma_gemm_kernel<true>,
                         cudaFuncAttributeMaxDynamicSharedMemorySize, GEMM_SMEM);
    cudaFuncSetAttribute(mma_gemm_kernel<false>,
                         cudaFuncAttributeMaxDynamicSharedMemorySize, GEMM_SMEM);
    cudaFuncSetAttribute(mma_attn_kernel,
                         cudaFuncAttributeMaxDynamicSharedMemorySize, ATT_SMEM);

    rms_split_x_kernel<<<N_TOK, 256>>>((const float4*)x, gamma);
    split_w_kernel<<<(DIM * QKV_N / 4) / 256, 256>>>((const float4*)w_qkv, wqh, wql);
    split_w_kernel<<<(DINNER * DIM / 4) / 256, 256>>>((const float4*)w_out, woh, wol);

    mma_gemm_kernel<true><<<dim3(QKV_N / 64, N_TOK / 128), 256, GEMM_SMEM>>>(
        xh, xl, wqh, wql, nullptr, qkvh, qkvl, N_TOK, QKV_N, DIM);

    mma_attn_kernel<<<dim3(64, 8, 2), 128, ATT_SMEM>>>(qkvh, qkvl);
    attn_merge_kernel<<<N_TOK, 256>>>();

    mma_gemm_kernel<false><<<dim3(DIM / 64, N_TOK / 128), 256, GEMM_SMEM>>>(
        aoh, aol, woh, wol, out, nullptr, nullptr, N_TOK, DIM, DINNER);
}

// round 14
// speedup vs baseline: 1.0577x; 1.0577x over previous
#include <cuda_runtime.h>
#include <cuda_bf16.h>
#include <cuda_fp16.h>
#include <math.h>
#include <stdint.h>

#define N_TOK   4096
#define DIM     1024
#define HEADS   8
#define DHEAD   64
#define DINNER  512
#define QKV_N   1536

// Scratch (allocation-free rule: __device__ globals)
__device__ __nv_bfloat16 g_xh[(size_t)N_TOK * DIM],     g_xl[(size_t)N_TOK * DIM];
__device__ __nv_bfloat16 g_wqh[(size_t)DIM * QKV_N],    g_wql[(size_t)DIM * QKV_N];
__device__ __nv_bfloat16 g_woh[(size_t)DINNER * DIM],   g_wol[(size_t)DINNER * DIM];
// qkv outputs: q,k as fp16 hi/lo pairs (cols 0-1023), v as single fp16
__device__ __half g_qkh[(size_t)N_TOK * 1024], g_qkl[(size_t)N_TOK * 1024];
__device__ __half g_vf[(size_t)N_TOK * DINNER];
__device__ __nv_bfloat16 g_aoh[(size_t)N_TOK * DINNER], g_aol[(size_t)N_TOK * DINNER];

// ---------------------------------------------------------------------------
// Helpers
// ---------------------------------------------------------------------------
__device__ __forceinline__ void mma16816(float* c,
    uint32_t a0, uint32_t a1, uint32_t a2, uint32_t a3,
    uint32_t b0, uint32_t b1) {
    asm volatile(
        "mma.sync.aligned.m16n8k16.row.col.f32.bf16.bf16.f32 "
        "{%0,%1,%2,%3}, {%4,%5,%6,%7}, {%8,%9}, {%0,%1,%2,%3};"
        : "+f"(c[0]), "+f"(c[1]), "+f"(c[2]), "+f"(c[3])
        : "r"(a0), "r"(a1), "r"(a2), "r"(a3), "r"(b0), "r"(b1));
}
__device__ __forceinline__ void mma16816h(float* c,
    uint32_t a0, uint32_t a1, uint32_t a2, uint32_t a3,
    uint32_t b0, uint32_t b1) {
    asm volatile(
        "mma.sync.aligned.m16n8k16.row.col.f32.f16.f16.f32 "
        "{%0,%1,%2,%3}, {%4,%5,%6,%7}, {%8,%9}, {%0,%1,%2,%3};"
        : "+f"(c[0]), "+f"(c[1]), "+f"(c[2]), "+f"(c[3])
        : "r"(a0), "r"(a1), "r"(a2), "r"(a3), "r"(b0), "r"(b1));
}
__device__ __forceinline__ void ldsm4(uint32_t& r0, uint32_t& r1,
                                      uint32_t& r2, uint32_t& r3, const void* p) {
    uint32_t a = (uint32_t)__cvta_generic_to_shared(p);
    asm volatile("ldmatrix.sync.aligned.m8n8.x4.shared.b16 {%0,%1,%2,%3}, [%4];"
                 : "=r"(r0), "=r"(r1), "=r"(r2), "=r"(r3) : "r"(a));
}
__device__ __forceinline__ void ldsm4t(uint32_t& r0, uint32_t& r1,
                                       uint32_t& r2, uint32_t& r3, const void* p) {
    uint32_t a = (uint32_t)__cvta_generic_to_shared(p);
    asm volatile("ldmatrix.sync.aligned.m8n8.x4.trans.shared.b16 {%0,%1,%2,%3}, [%4];"
                 : "=r"(r0), "=r"(r1), "=r"(r2), "=r"(r3) : "r"(a));
}
__device__ __forceinline__ void split2(float v0, float v1,
                                       uint32_t& hi, uint32_t& lo) {
    __nv_bfloat16 h0 = __float2bfloat16_rn(v0);
    __nv_bfloat16 h1 = __float2bfloat16_rn(v1);
    __nv_bfloat16 l0 = __float2bfloat16_rn(v0 - __bfloat162float(h0));
    __nv_bfloat16 l1 = __float2bfloat16_rn(v1 - __bfloat162float(h1));
    __nv_bfloat162 hp; hp.x = h0; hp.y = h1;
    __nv_bfloat162 lp; lp.x = l0; lp.y = l1;
    hi = *(uint32_t*)&hp;
    lo = *(uint32_t*)&lp;
}
// fp16 hi/lo split (22-bit effective mantissa)
__device__ __forceinline__ void split2h(float v0, float v1,
                                        uint32_t& hi, uint32_t& lo) {
    __half h0 = __float2half_rn(v0);
    __half h1 = __float2half_rn(v1);
    __half l0 = __float2half_rn(v0 - __half2float(h0));
    __half l1 = __float2half_rn(v1 - __half2float(h1));
    __half2 hp; hp.x = h0; hp.y = h1;
    __half2 lp; lp.x = l0; lp.y = l1;
    hi = *(uint32_t*)&hp;
    lo = *(uint32_t*)&lp;
}
__device__ __forceinline__ void cp16(uint32_t d, const void* s) {
    asm volatile("cp.async.cg.shared.global [%0], [%1], 16;" :: "r"(d), "l"(s));
}
__device__ __forceinline__ void cpcommit() { asm volatile("cp.async.commit_group;" ::: "memory"); }
__device__ __forceinline__ void cpwait0()  { asm volatile("cp.async.wait_group 0;" ::: "memory"); }
__device__ __forceinline__ void cpwait1()  { asm volatile("cp.async.wait_group 1;" ::: "memory"); }

// ---------------------------------------------------------------------------
// Kernel 1: fused rmsnorm + gamma + bf16 hi/lo split of x.
// ---------------------------------------------------------------------------
__global__ __launch_bounds__(256)
void rms_split_x_kernel(const float4* __restrict__ x,
                        const float* __restrict__ gamma) {
    int row = blockIdx.x;
    float4 v = x[(size_t)row * 256 + threadIdx.x];
    float s = v.x * v.x + v.y * v.y + v.z * v.z + v.w * v.w;
    #pragma unroll
    for (int o = 16; o; o >>= 1) s += __shfl_xor_sync(0xffffffffu, s, o);
    __shared__ float ws[8];
    if ((threadIdx.x & 31) == 0) ws[threadIdx.x >> 5] = s;
    __syncthreads();
    float t = 0.f;
    #pragma unroll
    for (int i = 0; i < 8; i++) t += ws[i];
    float sc = 32.0f / fmaxf(sqrtf(t), 1e-12f);

    int col = threadIdx.x * 4;
    float4 gm = *(const float4*)(gamma + col);
    uint32_t h0, l0, h1, l1;
    split2(v.x * sc * gm.x, v.y * sc * gm.y, h0, l0);
    split2(v.z * sc * gm.z, v.w * sc * gm.w, h1, l1);
    size_t o4 = (size_t)row * DIM + col;
    *(uint2*)&g_xh[o4] = make_uint2(h0, h1);
    *(uint2*)&g_xl[o4] = make_uint2(l0, l1);
}

__global__ void split_w_kernel(const float4* __restrict__ w,
                               __nv_bfloat16* __restrict__ hi,
                               __nv_bfloat16* __restrict__ lo) {
    int i = blockIdx.x * 256 + threadIdx.x;
    float4 v = w[i];
    uint32_t h0, l0, h1, l1;
    split2(v.x, v.y, h0, l0);
    split2(v.z, v.w, h1, l1);
    *(uint2*)&hi[(size_t)4 * i] = make_uint2(h0, h1);
    *(uint2*)&lo[(size_t)4 * i] = make_uint2(l0, l1);
}

// ---------------------------------------------------------------------------
// bf16-split HMMA GEMM: 128x64 tile, BK=32, cp.async 2-stage, ldmatrix.x4.
// QKV_OUT epilogue: cols < 1024 (q,k) -> fp16 hi/lo pairs into g_qkh/g_qkl
// (row stride 1024); cols >= 1024 (v) -> single fp16 into g_vf (stride 512).
// ---------------------------------------------------------------------------
#define GA_ELE (128 * 40)
#define GB_ELE (32 * 72)
#define GSTAGE_ELE (2 * GA_ELE + 2 * GB_ELE)
#define GEMM_SMEM (2 * GSTAGE_ELE * 2)

template <bool QKV_OUT>
__global__ __launch_bounds__(256)
void mma_gemm_kernel(const __nv_bfloat16* __restrict__ Ah,
                     const __nv_bfloat16* __restrict__ Al,
                     const __nv_bfloat16* __restrict__ Bh,
                     const __nv_bfloat16* __restrict__ Bl,
                     float* __restrict__ C,
                     __half* __restrict__ Ch,
                     __half* __restrict__ Cl,
                     __half* __restrict__ Vf,
                     int M, int N, int K) {
    extern __shared__ __align__(16) __nv_bfloat16 smg[];
    uint32_t smg_u = (uint32_t)__cvta_generic_to_shared(smg);
    int tid = threadIdx.x;
    int wid = tid >> 5, lane = tid & 31;
    int g = lane >> 2, t = lane & 3;
    int wm = wid & 3, wn = wid >> 2;
    int m0 = blockIdx.y * 128, n0 = blockIdx.x * 64;

    int arow = ((lane >> 3) & 1) * 8 + (lane & 7);
    int acol = (lane >> 4) * 8;
    int brow = lane & 15;
    int bcol = (lane >> 4) * 8;

    int a0r = tid >> 2,         a0k = (tid & 3) * 8;
    int a1r = (tid + 256) >> 2, a1k = ((tid + 256) & 3) * 8;
    int lbr = tid >> 3,         lbn = (tid & 7) * 8;

    #define G_LOAD(buf_, k0_) do {                                              \
        uint32_t sb = smg_u + (buf_) * (GSTAGE_ELE * 2);                        \
        cp16(sb + (a0r * 40 + a0k) * 2,                                         \
             Ah + (size_t)(m0 + a0r) * K + (k0_) + a0k);                        \
        cp16(sb + (a1r * 40 + a1k) * 2,                                         \
             Ah + (size_t)(m0 + a1r) * K + (k0_) + a1k);                        \
        cp16(sb + (GA_ELE + a0r * 40 + a0k) * 2,                                \
             Al + (size_t)(m0 + a0r) * K + (k0_) + a0k);                        \
        cp16(sb + (GA_ELE + a1r * 40 + a1k) * 2,                                \
             Al + (size_t)(m0 + a1r) * K + (k0_) + a1k);                        \
        cp16(sb + (2 * GA_ELE + lbr * 72 + lbn) * 2,                            \
             Bh + (size_t)((k0_) + lbr) * N + n0 + lbn);                        \
        cp16(sb + (2 * GA_ELE + GB_ELE + lbr * 72 + lbn) * 2,                   \
             Bl + (size_t)((k0_) + lbr) * N + n0 + lbn);                        \
        cpcommit();                                                             \
    } while (0)

    float c[2][4][4];
    #pragma unroll
    for (int mt = 0; mt < 2; mt++)
        #pragma unroll
        for (int nt = 0; nt < 4; nt++)
            #pragma unroll
            for (int e = 0; e < 4; e++) c[mt][nt][e] = 0.f;

    const int S = K / 32;
    G_LOAD(0, 0);
    for (int s = 0; s < S; s++) {
        if (s + 1 < S) { G_LOAD((s + 1) & 1, (s + 1) * 32); cpwait1(); }
        else           { cpwait0(); }
        __syncthreads();

        const __nv_bfloat16* stg = smg + (s & 1) * GSTAGE_ELE;
        const __nv_bfloat16* As0 = stg;
        const __nv_bfloat16* As1 = stg + GA_ELE;
        const __nv_bfloat16* Bs0 = stg + 2 * GA_ELE;
        const __nv_bfloat16* Bs1 = stg + 2 * GA_ELE + GB_ELE;

        #pragma unroll
        for (int kk = 0; kk < 32; kk += 16) {
            uint32_t ah[2][4], al[2][4];
            #pragma unroll
            for (int mt = 0; mt < 2; mt++) {
                int r = wm * 32 + mt * 16;
                ldsm4(ah[mt][0], ah[mt][1], ah[mt][2], ah[mt][3],
                      &As0[(r + arow) * 40 + kk + acol]);
                ldsm4(al[mt][0], al[mt][1], al[mt][2], al[mt][3],
                      &As1[(r + arow) * 40 + kk + acol]);
            }
            #pragma unroll
            for (int p2 = 0; p2 < 2; p2++) {
                uint32_t bh0, bh1, bh2, bh3, bl0, bl1, bl2, bl3;
                ldsm4t(bh0, bh1, bh2, bh3,
                       &Bs0[(kk + brow) * 72 + wn * 32 + p2 * 16 + bcol]);
                ldsm4t(bl0, bl1, bl2, bl3,
                       &Bs1[(kk + brow) * 72 + wn * 32 + p2 * 16 + bcol]);
                mma16816(c[0][2*p2],   ah[0][0], ah[0][1], ah[0][2], ah[0][3], bh0, bh1);
                mma16816(c[0][2*p2+1], ah[0][0], ah[0][1], ah[0][2], ah[0][3], bh2, bh3);
                mma16816(c[1][2*p2],   ah[1][0], ah[1][1], ah[1][2], ah[1][3], bh0, bh1);
                mma16816(c[1][2*p2+1], ah[1][0], ah[1][1], ah[1][2], ah[1][3], bh2, bh3);
                mma16816(c[0][2*p2],   ah[0][0], ah[0][1], ah[0][2], ah[0][3], bl0, bl1);
                mma16816(c[0][2*p2+1], ah[0][0], ah[0][1], ah[0][2], ah[0][3], bl2, bl3);
                mma16816(c[1][2*p2],   ah[1][0], ah[1][1], ah[1][2], ah[1][3], bl0, bl1);
                mma16816(c[1][2*p2+1], ah[1][0], ah[1][1], ah[1][2], ah[1][3], bl2, bl3);
                mma16816(c[0][2*p2],   al[0][0], al[0][1], al[0][2], al[0][3], bh0, bh1);
                mma16816(c[0][2*p2+1], al[0][0], al[0][1], al[0][2], al[0][3], bh2, bh3);
                mma16816(c[1][2*p2],   al[1][0], al[1][1], al[1][2], al[1][3], bh0, bh1);
                mma16816(c[1][2*p2+1], al[1][0], al[1][1], al[1][2], al[1][3], bh2, bh3);
            }
        }
        __syncthreads();
    }

    #pragma unroll
    for (int mt = 0; mt < 2; mt++) {
        #pragma unroll
        for (int nt = 0; nt < 4; nt++) {
            int rowA = m0 + wm * 32 + mt * 16 + g;
            int col = n0 + wn * 32 + nt * 8 + 2 * t;
            if (QKV_OUT) {
                if (col < 2 * DINNER) {      // q,k: fp16 hi/lo pair
                    uint32_t hi, lo;
                    split2h(c[mt][nt][0], c[mt][nt][1], hi, lo);
                    *(uint32_t*)&Ch[(size_t)rowA * 1024 + col] = hi;
                    *(uint32_t*)&Cl[(size_t)rowA * 1024 + col] = lo;
                    split2h(c[mt][nt][2], c[mt][nt][3], hi, lo);
                    *(uint32_t*)&Ch[(size_t)(rowA + 8) * 1024 + col] = hi;
                    *(uint32_t*)&Cl[(size_t)(rowA + 8) * 1024 + col] = lo;
                } else {                     // v: single fp16
                    int vc = col - 2 * DINNER;
                    __half2 p0 = __floats2half2_rn(c[mt][nt][0], c[mt][nt][1]);
                    __half2 p1 = __floats2half2_rn(c[mt][nt][2], c[mt][nt][3]);
                    *(__half2*)&Vf[(size_t)rowA * DINNER + vc] = p0;
                    *(__half2*)&Vf[(size_t)(rowA + 8) * DINNER + vc] = p1;
                }
            } else {
                *(float2*)&C[(size_t)rowA * N + col] =
                    make_float2(c[mt][nt][0], c[mt][nt][1]);
                *(float2*)&C[(size_t)(rowA + 8) * N + col] =
                    make_float2(c[mt][nt][2], c[mt][nt][3]);
            }
        }
    }
    #undef G_LOAD
}

// ---------------------------------------------------------------------------
// Flash attention, fp16 path: S = 3-product fp16 (q,k hi/lo pairs),
// PV = 2-product (P split fp16, V single fp16). 64-row Q tiles, 4 warps.
// K/V cp.async double-buffered; stage = Kh | Kl | V (27.6 KB) -> 4 CTAs/SM.
// ---------------------------------------------------------------------------
#define AT_ARR 4608
#define AT_STAGE (3 * AT_ARR)            // Kh | Kl | V
#define ATT_SMEM (2 * AT_STAGE * 2)      // 55296 bytes

__global__ __launch_bounds__(128)
void mma_attn_kernel(const __half* __restrict__ qkh,
                     const __half* __restrict__ qkl,
                     const __half* __restrict__ vf,
                     __nv_bfloat16* __restrict__ aoh,
                     __nv_bfloat16* __restrict__ aol) {
    extern __shared__ __align__(16) __half smb[];
    uint32_t smb_u = (uint32_t)__cvta_generic_to_shared(smb);

    int qt = 63 - blockIdx.x;          // heavy tiles first
    int h = blockIdx.y;
    int tid = threadIdx.x;
    int wid = tid >> 5, lane = tid & 31;
    int g = lane >> 2, t = lane & 3;
    int r0 = wid * 16;
    int gA = qt * 64 + r0 + g;

    int krow = ((lane >> 4) & 1) * 8 + (lane & 7);
    int kcol = ((lane >> 3) & 1) * 8;
    int vrow = lane & 15;
    int vcol = (lane >> 4) * 8;

    // stage loader: Kh, Kl (from qk pairs, col offset +512), V single
    #define LOAD_KV(kt_, buf_) do {                                            \
        uint32_t sbase = smb_u + (buf_) * (AT_STAGE * 2);                      \
        _Pragma("unroll")                                                      \
        for (int j = 0; j < 4; j++) {                                          \
            int p = tid + j * 128;                                             \
            int rr = p >> 3, c8 = (p & 7) * 8;                                 \
            uint32_t dso = rr * 144 + c8 * 2;                                  \
            size_t bk = (size_t)((kt_) * 64 + rr) * 1024 + 512 + h * DHEAD + c8; \
            size_t bv = (size_t)((kt_) * 64 + rr) * DINNER + h * DHEAD + c8;   \
            cp16(sbase + dso,                  qkh + bk);                      \
            cp16(sbase + AT_ARR * 2 + dso,     qkl + bk);                      \
            cp16(sbase + 2 * AT_ARR * 2 + dso, vf + bv);                       \
        }                                                                      \
        cpcommit();                                                            \
    } while (0)

    uint32_t ahq[4][4], alq[4][4];
    {
        size_t rA = (size_t)gA * 1024 + h * DHEAD;
        size_t rB = (size_t)(gA + 8) * 1024 + h * DHEAD;
        #pragma unroll
        for (int d16 = 0; d16 < 4; d16++) {
            int cA = d16 * 16 + 2 * t, cB = d16 * 16 + 8 + 2 * t;
            ahq[d16][0] = *(const uint32_t*)&qkh[rA + cA];
            ahq[d16][1] = *(const uint32_t*)&qkh[rB + cA];
            ahq[d16][2] = *(const uint32_t*)&qkh[rA + cB];
            ahq[d16][3] = *(const uint32_t*)&qkh[rB + cB];
            alq[d16][0] = *(const uint32_t*)&qkl[rA + cA];
            alq[d16][1] = *(const uint32_t*)&qkl[rB + cA];
            alq[d16][2] = *(const uint32_t*)&qkl[rA + cB];
            alq[d16][3] = *(const uint32_t*)&qkl[rB + cB];
        }
    }

    float o[8][4];
    #pragma unroll
    for (int nt = 0; nt < 8; nt++)
        #pragma unroll
        for (int e = 0; e < 4; e++) o[nt][e] = 0.f;
    float m[2] = {-1e30f, -1e30f}, l[2] = {0.f, 0.f};

    LOAD_KV(0, 0);

    for (int kt = 0; kt <= qt; kt++) {
        __syncthreads();
        if (kt < qt) { LOAD_KV(kt + 1, (kt + 1) & 1); cpwait1(); }
        else         { cpwait0(); }
        __syncthreads();

        const __half* stg = smb + (kt & 1) * AT_STAGE;
        const __half* Kh = stg;
        const __half* Kl = stg + AT_ARR;
        const __half* Vs = stg + 2 * AT_ARR;

        float sc[8][4];
        #pragma unroll
        for (int nt = 0; nt < 8; nt++)
            #pragma unroll
            for (int e = 0; e < 4; e++) sc[nt][e] = 0.f;

        #pragma unroll
        for (int d16 = 0; d16 < 4; d16++) {
            #pragma unroll
            for (int p2 = 0; p2 < 4; p2++) {
                uint32_t bh0, bh1, bh2, bh3, bl0, bl1, bl2, bl3;
                ldsm4(bh0, bh1, bh2, bh3,
                      &Kh[(p2 * 16 + krow) * 72 + d16 * 16 + kcol]);
                ldsm4(bl0, bl1, bl2, bl3,
                      &Kl[(p2 * 16 + krow) * 72 + d16 * 16 + kcol]);
                mma16816h(sc[2*p2],   ahq[d16][0], ahq[d16][1], ahq[d16][2], ahq[d16][3], bh0, bh1);
                mma16816h(sc[2*p2+1], ahq[d16][0], ahq[d16][1], ahq[d16][2], ahq[d16][3], bh2, bh3);
                mma16816h(sc[2*p2],   ahq[d16][0], ahq[d16][1], ahq[d16][2], ahq[d16][3], bl0, bl1);
                mma16816h(sc[2*p2+1], ahq[d16][0], ahq[d16][1], ahq[d16][2], ahq[d16][3], bl2, bl3);
                mma16816h(sc[2*p2],   alq[d16][0], alq[d16][1], alq[d16][2], alq[d16][3], bh0, bh1);
                mma16816h(sc[2*p2+1], alq[d16][0], alq[d16][1], alq[d16][2], alq[d16][3], bh2, bh3);
            }
        }

        #pragma unroll
        for (int nt = 0; nt < 8; nt++)
            #pragma unroll
            for (int e = 0; e < 4; e++) sc[nt][e] *= 8.f;

        if (kt == qt) {
            #pragma unroll
            for (int nt = 0; nt < 8; nt++) {
                int colb = nt * 8 + 2 * t;
                int rA = r0 + g, rB = r0 + 8 + g;
                if (colb > rA)     sc[nt][0] = -1e30f;
                if (colb + 1 > rA) sc[nt][1] = -1e30f;
                if (colb > rB)     sc[nt][2] = -1e30f;
                if (colb + 1 > rB) sc[nt][3] = -1e30f;
            }
        }

        #pragma unroll
        for (int hf = 0; hf < 2; hf++) {
            float mx = -1e30f;
            #pragma unroll
            for (int nt = 0; nt < 8; nt++) {
                mx = fmaxf(mx, sc[nt][2 * hf]);
                mx = fmaxf(mx, sc[nt][2 * hf + 1]);
            }
            mx = fmaxf(mx, __shfl_xor_sync(0xffffffffu, mx, 1));
            mx = fmaxf(mx, __shfl_xor_sync(0xffffffffu, mx, 2));
            float mnew = fmaxf(m[hf], mx);
            float corr = __expf(m[hf] - mnew);
            m[hf] = mnew;
            float sum = 0.f;
            #pragma unroll
            for (int nt = 0; nt < 8; nt++) {
                float p0 = __expf(sc[nt][2 * hf] - mnew);
                float p1 = __expf(sc[nt][2 * hf + 1] - mnew);
                sc[nt][2 * hf] = p0;
                sc[nt][2 * hf + 1] = p1;
                sum += p0 + p1;
            }
            sum += __shfl_xor_sync(0xffffffffu, sum, 1);
            sum += __shfl_xor_sync(0xffffffffu, sum, 2);
            l[hf] = l[hf] * corr + sum;
            #pragma unroll
            for (int nt = 0; nt < 8; nt++) {
                o[nt][2 * hf] *= corr;
                o[nt][2 * hf + 1] *= corr;
            }
        }

        // P -> fp16 hi/lo fragments (near-exact pair)
        uint32_t phf[4][4], plf[4][4];
        #pragma unroll
        for (int kk = 0; kk < 4; kk++) {
            split2h(sc[2 * kk][0], sc[2 * kk][1], phf[kk][0], plf[kk][0]);
            split2h(sc[2 * kk][2], sc[2 * kk][3], phf[kk][1], plf[kk][1]);
            split2h(sc[2 * kk + 1][0], sc[2 * kk + 1][1], phf[kk][2], plf[kk][2]);
            split2h(sc[2 * kk + 1][2], sc[2 * kk + 1][3], phf[kk][3], plf[kk][3]);
        }

        // PV: 2 products (ph*V + pl*V), V single fp16
        #pragma unroll
        for (int kk = 0; kk < 4; kk++) {
            #pragma unroll
            for (int p2 = 0; p2 < 4; p2++) {
                uint32_t v0, v1, v2, v3;
                ldsm4t(v0, v1, v2, v3,
                       &Vs[(kk * 16 + vrow) * 72 + p2 * 16 + vcol]);
                mma16816h(o[2*p2],   phf[kk][0], phf[kk][1], phf[kk][2], phf[kk][3], v0, v1);
                mma16816h(o[2*p2+1], phf[kk][0], phf[kk][1], phf[kk][2], phf[kk][3], v2, v3);
                mma16816h(o[2*p2],   plf[kk][0], plf[kk][1], plf[kk][2], plf[kk][3], v0, v1);
                mma16816h(o[2*p2+1], plf[kk][0], plf[kk][1], plf[kk][2], plf[kk][3], v2, v3);
            }
        }
    }

    float inv0 = 1.f / l[0], inv1 = 1.f / l[1];
    #pragma unroll
    for (int nt = 0; nt < 8; nt++) {
        int col = h * DHEAD + nt * 8 + 2 * t;
        size_t rA = (size_t)gA * DINNER + col;
        size_t rB = (size_t)(gA + 8) * DINNER + col;
        uint32_t hi, lo;
        split2(o[nt][0] * inv0, o[nt][1] * inv0, hi, lo);
        *(uint32_t*)&aoh[rA] = hi;
        *(uint32_t*)&aol[rA] = lo;
        split2(o[nt][2] * inv1, o[nt][3] * inv1, hi, lo);
        *(uint32_t*)&aoh[rB] = hi;
        *(uint32_t*)&aol[rB] = lo;
    }
    #undef LOAD_KV
}

// ---------------------------------------------------------------------------
extern "C" void kernel_launch(void* const* d_in, const int* in_sizes, int n_in,
                              void* d_out, int out_size) {
    const float* x     = (const float*)d_in[0];
    const float* gamma = (const float*)d_in[1];
    const float* w_qkv = (const float*)d_in[2];
    const float* w_out = (const float*)d_in[3];
    float* out = (float*)d_out;

    __nv_bfloat16 *xh, *xl, *wqh, *wql, *woh, *wol, *aoh, *aol;
    __half *qkh, *qkl, *vf;
    cudaGetSymbolAddress((void**)&xh, g_xh);
    cudaGetSymbolAddress((void**)&xl, g_xl);
    cudaGetSymbolAddress((void**)&wqh, g_wqh);
    cudaGetSymbolAddress((void**)&wql, g_wql);
    cudaGetSymbolAddress((void**)&woh, g_woh);
    cudaGetSymbolAddress((void**)&wol, g_wol);
    cudaGetSymbolAddress((void**)&qkh, g_qkh);
    cudaGetSymbolAddress((void**)&qkl, g_qkl);
    cudaGetSymbolAddress((void**)&vf, g_vf);
    cudaGetSymbolAddress((void**)&aoh, g_aoh);
    cudaGetSymbolAddress((void**)&aol, g_aol);

    cudaFuncSetAttribute(mma_gemm_kernel<true>,
                         cudaFuncAttributeMaxDynamicSharedMemorySize, GEMM_SMEM);
    cudaFuncSetAttribute(mma_gemm_kernel<false>,
                         cudaFuncAttributeMaxDynamicSharedMemorySize, GEMM_SMEM);
    cudaFuncSetAttribute(mma_attn_kernel,
                         cudaFuncAttributeMaxDynamicSharedMemorySize, ATT_SMEM);

    rms_split_x_kernel<<<N_TOK, 256>>>((const float4*)x, gamma);
    split_w_kernel<<<(DIM * QKV_N / 4) / 256, 256>>>((const float4*)w_qkv, wqh, wql);
    split_w_kernel<<<(DINNER * DIM / 4) / 256, 256>>>((const float4*)w_out, woh, wol);

    mma_gemm_kernel<true><<<dim3(QKV_N / 64, N_TOK / 128), 256, GEMM_SMEM>>>(
        xh, xl, wqh, wql, nullptr, qkh, qkl, vf, N_TOK, QKV_N, DIM);

    mma_attn_kernel<<<dim3(64, 8), 128, ATT_SMEM>>>(qkh, qkl, vf, aoh, aol);

    mma_gemm_kernel<false><<<dim3(DIM / 64, N_TOK / 128), 256, GEMM_SMEM>>>(
        aoh, aol, woh, wol, out, nullptr, nullptr, nullptr, N_TOK, DIM, DINNER);
}

// round 15
// speedup vs baseline: 1.1025x; 1.0424x over previous
#include <cuda_runtime.h>
#include <cuda_bf16.h>
#include <cuda_fp16.h>
#include <math.h>
#include <stdint.h>

#define N_TOK   4096
#define DIM     1024
#define HEADS   8
#define DHEAD   64
#define DINNER  512
#define QKV_N   1536

// Scratch (allocation-free rule: __device__ globals) — all fp16 now
__device__ __half g_xh[(size_t)N_TOK * DIM],   g_xl[(size_t)N_TOK * DIM];
__device__ __half g_wqh[(size_t)DIM * QKV_N],  g_wql[(size_t)DIM * QKV_N];
__device__ __half g_woh[(size_t)DINNER * DIM];                 // lo never needed (2-product)
__device__ __half g_qkh[(size_t)N_TOK * 1024], g_qkl[(size_t)N_TOK * 1024];
__device__ __half g_vf[(size_t)N_TOK * DINNER];
__device__ __half g_aoh[(size_t)N_TOK * DINNER], g_aol[(size_t)N_TOK * DINNER];

// ---------------------------------------------------------------------------
// Helpers
// ---------------------------------------------------------------------------
__device__ __forceinline__ void mma16816h(float* c,
    uint32_t a0, uint32_t a1, uint32_t a2, uint32_t a3,
    uint32_t b0, uint32_t b1) {
    asm volatile(
        "mma.sync.aligned.m16n8k16.row.col.f32.f16.f16.f32 "
        "{%0,%1,%2,%3}, {%4,%5,%6,%7}, {%8,%9}, {%0,%1,%2,%3};"
        : "+f"(c[0]), "+f"(c[1]), "+f"(c[2]), "+f"(c[3])
        : "r"(a0), "r"(a1), "r"(a2), "r"(a3), "r"(b0), "r"(b1));
}
__device__ __forceinline__ void ldsm4(uint32_t& r0, uint32_t& r1,
                                      uint32_t& r2, uint32_t& r3, const void* p) {
    uint32_t a = (uint32_t)__cvta_generic_to_shared(p);
    asm volatile("ldmatrix.sync.aligned.m8n8.x4.shared.b16 {%0,%1,%2,%3}, [%4];"
                 : "=r"(r0), "=r"(r1), "=r"(r2), "=r"(r3) : "r"(a));
}
__device__ __forceinline__ void ldsm4t(uint32_t& r0, uint32_t& r1,
                                       uint32_t& r2, uint32_t& r3, const void* p) {
    uint32_t a = (uint32_t)__cvta_generic_to_shared(p);
    asm volatile("ldmatrix.sync.aligned.m8n8.x4.trans.shared.b16 {%0,%1,%2,%3}, [%4];"
                 : "=r"(r0), "=r"(r1), "=r"(r2), "=r"(r3) : "r"(a));
}
// fp16 hi/lo split (~22-bit effective mantissa)
__device__ __forceinline__ void split2h(float v0, float v1,
                                        uint32_t& hi, uint32_t& lo) {
    __half h0 = __float2half_rn(v0);
    __half h1 = __float2half_rn(v1);
    __half l0 = __float2half_rn(v0 - __half2float(h0));
    __half l1 = __float2half_rn(v1 - __half2float(h1));
    __half2 hp; hp.x = h0; hp.y = h1;
    __half2 lp; lp.x = l0; lp.y = l1;
    hi = *(uint32_t*)&hp;
    lo = *(uint32_t*)&lp;
}
__device__ __forceinline__ void cp16(uint32_t d, const void* s) {
    asm volatile("cp.async.cg.shared.global [%0], [%1], 16;" :: "r"(d), "l"(s));
}
__device__ __forceinline__ void cpcommit() { asm volatile("cp.async.commit_group;" ::: "memory"); }
__device__ __forceinline__ void cpwait0()  { asm volatile("cp.async.wait_group 0;" ::: "memory"); }
__device__ __forceinline__ void cpwait1()  { asm volatile("cp.async.wait_group 1;" ::: "memory"); }

// ---------------------------------------------------------------------------
// Kernel 1: fused rmsnorm + gamma + fp16 hi/lo split of x.
// ---------------------------------------------------------------------------
__global__ __launch_bounds__(256)
void rms_split_x_kernel(const float4* __restrict__ x,
                        const float* __restrict__ gamma) {
    int row = blockIdx.x;
    float4 v = x[(size_t)row * 256 + threadIdx.x];
    float s = v.x * v.x + v.y * v.y + v.z * v.z + v.w * v.w;
    #pragma unroll
    for (int o = 16; o; o >>= 1) s += __shfl_xor_sync(0xffffffffu, s, o);
    __shared__ float ws[8];
    if ((threadIdx.x & 31) == 0) ws[threadIdx.x >> 5] = s;
    __syncthreads();
    float t = 0.f;
    #pragma unroll
    for (int i = 0; i < 8; i++) t += ws[i];
    float sc = 32.0f / fmaxf(sqrtf(t), 1e-12f);

    int col = threadIdx.x * 4;
    float4 gm = *(const float4*)(gamma + col);
    uint32_t h0, l0, h1, l1;
    split2h(v.x * sc * gm.x, v.y * sc * gm.y, h0, l0);
    split2h(v.z * sc * gm.z, v.w * sc * gm.w, h1, l1);
    size_t o4 = (size_t)row * DIM + col;
    *(uint2*)&g_xh[o4] = make_uint2(h0, h1);
    *(uint2*)&g_xl[o4] = make_uint2(l0, l1);
}

// fp16 hi/lo pair split of weights
__global__ void split_w_kernel(const float4* __restrict__ w,
                               __half* __restrict__ hi,
                               __half* __restrict__ lo) {
    int i = blockIdx.x * 256 + threadIdx.x;
    float4 v = w[i];
    uint32_t h0, l0, h1, l1;
    split2h(v.x, v.y, h0, l0);
    split2h(v.z, v.w, h1, l1);
    *(uint2*)&hi[(size_t)4 * i] = make_uint2(h0, h1);
    *(uint2*)&lo[(size_t)4 * i] = make_uint2(l0, l1);
}
// single fp16 conversion (w_out: lo never needed)
__global__ void conv_w_kernel(const float4* __restrict__ w,
                              __half* __restrict__ hi) {
    int i = blockIdx.x * 256 + threadIdx.x;
    float4 v = w[i];
    __half2 p0 = __floats2half2_rn(v.x, v.y);
    __half2 p1 = __floats2half2_rn(v.z, v.w);
    *(__half2*)&hi[(size_t)4 * i] = p0;
    *(__half2*)&hi[(size_t)4 * i + 2] = p1;
}

// ---------------------------------------------------------------------------
// fp16-split HMMA GEMM: C = (Ah+Al) @ B, 128x64 tile, BK=32, cp.async 2-stage,
// ldmatrix.x4. Products: ah*bh, al*bh always; ah*bl only if use_bl (3-product).
// use_bl is uniform per CTA (qkv: q,k cols need 22-bit B; v cols don't).
// ---------------------------------------------------------------------------
#define GA_ELE (128 * 40)
#define GB_ELE (32 * 72)
#define GSTAGE_ELE (2 * GA_ELE + 2 * GB_ELE)
#define GEMM_SMEM (2 * GSTAGE_ELE * 2)

template <bool QKV_OUT>
__global__ __launch_bounds__(256)
void mma_gemm_kernel(const __half* __restrict__ Ah,
                     const __half* __restrict__ Al,
                     const __half* __restrict__ Bh,
                     const __half* __restrict__ Bl,   // may be unused
                     float* __restrict__ C,
                     __half* __restrict__ Ch,
                     __half* __restrict__ Cl,
                     __half* __restrict__ Vf,
                     int M, int N, int K, int bl_col_limit) {
    extern __shared__ __align__(16) __half smg[];
    uint32_t smg_u = (uint32_t)__cvta_generic_to_shared(smg);
    int tid = threadIdx.x;
    int wid = tid >> 5, lane = tid & 31;
    int g = lane >> 2, t = lane & 3;
    int wm = wid & 3, wn = wid >> 2;
    int m0 = blockIdx.y * 128, n0 = blockIdx.x * 64;
    bool use_bl = (n0 < bl_col_limit);

    int arow = ((lane >> 3) & 1) * 8 + (lane & 7);
    int acol = (lane >> 4) * 8;
    int brow = lane & 15;
    int bcol = (lane >> 4) * 8;

    int a0r = tid >> 2,         a0k = (tid & 3) * 8;
    int a1r = (tid + 256) >> 2, a1k = ((tid + 256) & 3) * 8;
    int lbr = tid >> 3,         lbn = (tid & 7) * 8;

    #define G_LOAD(buf_, k0_) do {                                              \
        uint32_t sb = smg_u + (buf_) * (GSTAGE_ELE * 2);                        \
        cp16(sb + (a0r * 40 + a0k) * 2,                                         \
             Ah + (size_t)(m0 + a0r) * K + (k0_) + a0k);                        \
        cp16(sb + (a1r * 40 + a1k) * 2,                                         \
             Ah + (size_t)(m0 + a1r) * K + (k0_) + a1k);                        \
        cp16(sb + (GA_ELE + a0r * 40 + a0k) * 2,                                \
             Al + (size_t)(m0 + a0r) * K + (k0_) + a0k);                        \
        cp16(sb + (GA_ELE + a1r * 40 + a1k) * 2,                                \
             Al + (size_t)(m0 + a1r) * K + (k0_) + a1k);                        \
        cp16(sb + (2 * GA_ELE + lbr * 72 + lbn) * 2,                            \
             Bh + (size_t)((k0_) + lbr) * N + n0 + lbn);                        \
        if (use_bl)                                                             \
            cp16(sb + (2 * GA_ELE + GB_ELE + lbr * 72 + lbn) * 2,               \
                 Bl + (size_t)((k0_) + lbr) * N + n0 + lbn);                    \
        cpcommit();                                                             \
    } while (0)

    float c[2][4][4];
    #pragma unroll
    for (int mt = 0; mt < 2; mt++)
        #pragma unroll
        for (int nt = 0; nt < 4; nt++)
            #pragma unroll
            for (int e = 0; e < 4; e++) c[mt][nt][e] = 0.f;

    const int S = K / 32;
    G_LOAD(0, 0);
    for (int s = 0; s < S; s++) {
        if (s + 1 < S) { G_LOAD((s + 1) & 1, (s + 1) * 32); cpwait1(); }
        else           { cpwait0(); }
        __syncthreads();

        const __half* stg = smg + (s & 1) * GSTAGE_ELE;
        const __half* As0 = stg;
        const __half* As1 = stg + GA_ELE;
        const __half* Bs0 = stg + 2 * GA_ELE;
        const __half* Bs1 = stg + 2 * GA_ELE + GB_ELE;

        #pragma unroll
        for (int kk = 0; kk < 32; kk += 16) {
            uint32_t ah[2][4], al[2][4];
            #pragma unroll
            for (int mt = 0; mt < 2; mt++) {
                int r = wm * 32 + mt * 16;
                ldsm4(ah[mt][0], ah[mt][1], ah[mt][2], ah[mt][3],
                      &As0[(r + arow) * 40 + kk + acol]);
                ldsm4(al[mt][0], al[mt][1], al[mt][2], al[mt][3],
                      &As1[(r + arow) * 40 + kk + acol]);
            }
            #pragma unroll
            for (int p2 = 0; p2 < 2; p2++) {
                uint32_t bh0, bh1, bh2, bh3;
                ldsm4t(bh0, bh1, bh2, bh3,
                       &Bs0[(kk + brow) * 72 + wn * 32 + p2 * 16 + bcol]);
                mma16816h(c[0][2*p2],   ah[0][0], ah[0][1], ah[0][2], ah[0][3], bh0, bh1);
                mma16816h(c[0][2*p2+1], ah[0][0], ah[0][1], ah[0][2], ah[0][3], bh2, bh3);
                mma16816h(c[1][2*p2],   ah[1][0], ah[1][1], ah[1][2], ah[1][3], bh0, bh1);
                mma16816h(c[1][2*p2+1], ah[1][0], ah[1][1], ah[1][2], ah[1][3], bh2, bh3);
                mma16816h(c[0][2*p2],   al[0][0], al[0][1], al[0][2], al[0][3], bh0, bh1);
                mma16816h(c[0][2*p2+1], al[0][0], al[0][1], al[0][2], al[0][3], bh2, bh3);
                mma16816h(c[1][2*p2],   al[1][0], al[1][1], al[1][2], al[1][3], bh0, bh1);
                mma16816h(c[1][2*p2+1], al[1][0], al[1][1], al[1][2], al[1][3], bh2, bh3);
                if (use_bl) {
                    uint32_t bl0, bl1, bl2, bl3;
                    ldsm4t(bl0, bl1, bl2, bl3,
                           &Bs1[(kk + brow) * 72 + wn * 32 + p2 * 16 + bcol]);
                    mma16816h(c[0][2*p2],   ah[0][0], ah[0][1], ah[0][2], ah[0][3], bl0, bl1);
                    mma16816h(c[0][2*p2+1], ah[0][0], ah[0][1], ah[0][2], ah[0][3], bl2, bl3);
                    mma16816h(c[1][2*p2],   ah[1][0], ah[1][1], ah[1][2], ah[1][3], bl0, bl1);
                    mma16816h(c[1][2*p2+1], ah[1][0], ah[1][1], ah[1][2], ah[1][3], bl2, bl3);
                }
            }
        }
        __syncthreads();
    }

    #pragma unroll
    for (int mt = 0; mt < 2; mt++) {
        #pragma unroll
        for (int nt = 0; nt < 4; nt++) {
            int rowA = m0 + wm * 32 + mt * 16 + g;
            int col = n0 + wn * 32 + nt * 8 + 2 * t;
            if (QKV_OUT) {
                if (col < 2 * DINNER) {      // q,k: fp16 hi/lo pair
                    uint32_t hi, lo;
                    split2h(c[mt][nt][0], c[mt][nt][1], hi, lo);
                    *(uint32_t*)&Ch[(size_t)rowA * 1024 + col] = hi;
                    *(uint32_t*)&Cl[(size_t)rowA * 1024 + col] = lo;
                    split2h(c[mt][nt][2], c[mt][nt][3], hi, lo);
                    *(uint32_t*)&Ch[(size_t)(rowA + 8) * 1024 + col] = hi;
                    *(uint32_t*)&Cl[(size_t)(rowA + 8) * 1024 + col] = lo;
                } else {                     // v: single fp16
                    int vc = col - 2 * DINNER;
                    __half2 p0 = __floats2half2_rn(c[mt][nt][0], c[mt][nt][1]);
                    __half2 p1 = __floats2half2_rn(c[mt][nt][2], c[mt][nt][3]);
                    *(__half2*)&Vf[(size_t)rowA * DINNER + vc] = p0;
                    *(__half2*)&Vf[(size_t)(rowA + 8) * DINNER + vc] = p1;
                }
            } else {
                *(float2*)&C[(size_t)rowA * N + col] =
                    make_float2(c[mt][nt][0], c[mt][nt][1]);
                *(float2*)&C[(size_t)(rowA + 8) * N + col] =
                    make_float2(c[mt][nt][2], c[mt][nt][3]);
            }
        }
    }
    #undef G_LOAD
}

// ---------------------------------------------------------------------------
// Flash attention (R14 version): S = 3-product fp16 (q,k hi/lo pairs),
// PV = 2-product (P split fp16, V single fp16). 64-row Q tiles, 4 warps,
// cp.async double-buffered stages (Kh | Kl | V). Epilogue emits fp16 ao pairs.
// ---------------------------------------------------------------------------
#define AT_ARR 4608
#define AT_STAGE (3 * AT_ARR)
#define ATT_SMEM (2 * AT_STAGE * 2)

__global__ __launch_bounds__(128)
void mma_attn_kernel(const __half* __restrict__ qkh,
                     const __half* __restrict__ qkl,
                     const __half* __restrict__ vf,
                     __half* __restrict__ aoh,
                     __half* __restrict__ aol) {
    extern __shared__ __align__(16) __half smb[];
    uint32_t smb_u = (uint32_t)__cvta_generic_to_shared(smb);

    int qt = 63 - blockIdx.x;          // heavy tiles first
    int h = blockIdx.y;
    int tid = threadIdx.x;
    int wid = tid >> 5, lane = tid & 31;
    int g = lane >> 2, t = lane & 3;
    int r0 = wid * 16;
    int gA = qt * 64 + r0 + g;

    int krow = ((lane >> 4) & 1) * 8 + (lane & 7);
    int kcol = ((lane >> 3) & 1) * 8;
    int vrow = lane & 15;
    int vcol = (lane >> 4) * 8;

    #define LOAD_KV(kt_, buf_) do {                                            \
        uint32_t sbase = smb_u + (buf_) * (AT_STAGE * 2);                      \
        _Pragma("unroll")                                                      \
        for (int j = 0; j < 4; j++) {                                          \
            int p = tid + j * 128;                                             \
            int rr = p >> 3, c8 = (p & 7) * 8;                                 \
            uint32_t dso = rr * 144 + c8 * 2;                                  \
            size_t bk = (size_t)((kt_) * 64 + rr) * 1024 + 512 + h * DHEAD + c8; \
            size_t bv = (size_t)((kt_) * 64 + rr) * DINNER + h * DHEAD + c8;   \
            cp16(sbase + dso,                  qkh + bk);                      \
            cp16(sbase + AT_ARR * 2 + dso,     qkl + bk);                      \
            cp16(sbase + 2 * AT_ARR * 2 + dso, vf + bv);                       \
        }                                                                      \
        cpcommit();                                                            \
    } while (0)

    uint32_t ahq[4][4], alq[4][4];
    {
        size_t rA = (size_t)gA * 1024 + h * DHEAD;
        size_t rB = (size_t)(gA + 8) * 1024 + h * DHEAD;
        #pragma unroll
        for (int d16 = 0; d16 < 4; d16++) {
            int cA = d16 * 16 + 2 * t, cB = d16 * 16 + 8 + 2 * t;
            ahq[d16][0] = *(const uint32_t*)&qkh[rA + cA];
            ahq[d16][1] = *(const uint32_t*)&qkh[rB + cA];
            ahq[d16][2] = *(const uint32_t*)&qkh[rA + cB];
            ahq[d16][3] = *(const uint32_t*)&qkh[rB + cB];
            alq[d16][0] = *(const uint32_t*)&qkl[rA + cA];
            alq[d16][1] = *(const uint32_t*)&qkl[rB + cA];
            alq[d16][2] = *(const uint32_t*)&qkl[rA + cB];
            alq[d16][3] = *(const uint32_t*)&qkl[rB + cB];
        }
    }

    float o[8][4];
    #pragma unroll
    for (int nt = 0; nt < 8; nt++)
        #pragma unroll
        for (int e = 0; e < 4; e++) o[nt][e] = 0.f;
    float m[2] = {-1e30f, -1e30f}, l[2] = {0.f, 0.f};

    LOAD_KV(0, 0);

    for (int kt = 0; kt <= qt; kt++) {
        __syncthreads();
        if (kt < qt) { LOAD_KV(kt + 1, (kt + 1) & 1); cpwait1(); }
        else         { cpwait0(); }
        __syncthreads();

        const __half* stg = smb + (kt & 1) * AT_STAGE;
        const __half* Kh = stg;
        const __half* Kl = stg + AT_ARR;
        const __half* Vs = stg + 2 * AT_ARR;

        float sc[8][4];
        #pragma unroll
        for (int nt = 0; nt < 8; nt++)
            #pragma unroll
            for (int e = 0; e < 4; e++) sc[nt][e] = 0.f;

        #pragma unroll
        for (int d16 = 0; d16 < 4; d16++) {
            #pragma unroll
            for (int p2 = 0; p2 < 4; p2++) {
                uint32_t bh0, bh1, bh2, bh3, bl0, bl1, bl2, bl3;
                ldsm4(bh0, bh1, bh2, bh3,
                      &Kh[(p2 * 16 + krow) * 72 + d16 * 16 + kcol]);
                ldsm4(bl0, bl1, bl2, bl3,
                      &Kl[(p2 * 16 + krow) * 72 + d16 * 16 + kcol]);
                mma16816h(sc[2*p2],   ahq[d16][0], ahq[d16][1], ahq[d16][2], ahq[d16][3], bh0, bh1);
                mma16816h(sc[2*p2+1], ahq[d16][0], ahq[d16][1], ahq[d16][2], ahq[d16][3], bh2, bh3);
                mma16816h(sc[2*p2],   ahq[d16][0], ahq[d16][1], ahq[d16][2], ahq[d16][3], bl0, bl1);
                mma16816h(sc[2*p2+1], ahq[d16][0], ahq[d16][1], ahq[d16][2], ahq[d16][3], bl2, bl3);
                mma16816h(sc[2*p2],   alq[d16][0], alq[d16][1], alq[d16][2], alq[d16][3], bh0, bh1);
                mma16816h(sc[2*p2+1], alq[d16][0], alq[d16][1], alq[d16][2], alq[d16][3], bh2, bh3);
            }
        }

        #pragma unroll
        for (int nt = 0; nt < 8; nt++)
            #pragma unroll
            for (int e = 0; e < 4; e++) sc[nt][e] *= 8.f;

        if (kt == qt) {
            #pragma unroll
            for (int nt = 0; nt < 8; nt++) {
                int colb = nt * 8 + 2 * t;
                int rA = r0 + g, rB = r0 + 8 + g;
                if (colb > rA)     sc[nt][0] = -1e30f;
                if (colb + 1 > rA) sc[nt][1] = -1e30f;
                if (colb > rB)     sc[nt][2] = -1e30f;
                if (colb + 1 > rB) sc[nt][3] = -1e30f;
            }
        }

        #pragma unroll
        for (int hf = 0; hf < 2; hf++) {
            float mx = -1e30f;
            #pragma unroll
            for (int nt = 0; nt < 8; nt++) {
                mx = fmaxf(mx, sc[nt][2 * hf]);
                mx = fmaxf(mx, sc[nt][2 * hf + 1]);
            }
            mx = fmaxf(mx, __shfl_xor_sync(0xffffffffu, mx, 1));
            mx = fmaxf(mx, __shfl_xor_sync(0xffffffffu, mx, 2));
            float mnew = fmaxf(m[hf], mx);
            float corr = __expf(m[hf] - mnew);
            m[hf] = mnew;
            float sum = 0.f;
            #pragma unroll
            for (int nt = 0; nt < 8; nt++) {
                float p0 = __expf(sc[nt][2 * hf] - mnew);
                float p1 = __expf(sc[nt][2 * hf + 1] - mnew);
                sc[nt][2 * hf] = p0;
                sc[nt][2 * hf + 1] = p1;
                sum += p0 + p1;
            }
            sum += __shfl_xor_sync(0xffffffffu, sum, 1);
            sum += __shfl_xor_sync(0xffffffffu, sum, 2);
            l[hf] = l[hf] * corr + sum;
            #pragma unroll
            for (int nt = 0; nt < 8; nt++) {
                o[nt][2 * hf] *= corr;
                o[nt][2 * hf + 1] *= corr;
            }
        }

        uint32_t phf[4][4], plf[4][4];
        #pragma unroll
        for (int kk = 0; kk < 4; kk++) {
            split2h(sc[2 * kk][0], sc[2 * kk][1], phf[kk][0], plf[kk][0]);
            split2h(sc[2 * kk][2], sc[2 * kk][3], phf[kk][1], plf[kk][1]);
            split2h(sc[2 * kk + 1][0], sc[2 * kk + 1][1], phf[kk][2], plf[kk][2]);
            split2h(sc[2 * kk + 1][2], sc[2 * kk + 1][3], phf[kk][3], plf[kk][3]);
        }

        #pragma unroll
        for (int kk = 0; kk < 4; kk++) {
            #pragma unroll
            for (int p2 = 0; p2 < 4; p2++) {
                uint32_t v0, v1, v2, v3;
                ldsm4t(v0, v1, v2, v3,
                       &Vs[(kk * 16 + vrow) * 72 + p2 * 16 + vcol]);
                mma16816h(o[2*p2],   phf[kk][0], phf[kk][1], phf[kk][2], phf[kk][3], v0, v1);
                mma16816h(o[2*p2+1], phf[kk][0], phf[kk][1], phf[kk][2], phf[kk][3], v2, v3);
                mma16816h(o[2*p2],   plf[kk][0], plf[kk][1], plf[kk][2], plf[kk][3], v0, v1);
                mma16816h(o[2*p2+1], plf[kk][0], plf[kk][1], plf[kk][2], plf[kk][3], v2, v3);
            }
        }
    }

    float inv0 = 1.f / l[0], inv1 = 1.f / l[1];
    #pragma unroll
    for (int nt = 0; nt < 8; nt++) {
        int col = h * DHEAD + nt * 8 + 2 * t;
        size_t rA = (size_t)gA * DINNER + col;
        size_t rB = (size_t)(gA + 8) * DINNER + col;
        uint32_t hi, lo;
        split2h(o[nt][0] * inv0, o[nt][1] * inv0, hi, lo);
        *(uint32_t*)&aoh[rA] = hi;
        *(uint32_t*)&aol[rA] = lo;
        split2h(o[nt][2] * inv1, o[nt][3] * inv1, hi, lo);
        *(uint32_t*)&aoh[rB] = hi;
        *(uint32_t*)&aol[rB] = lo;
    }
    #undef LOAD_KV
}

// ---------------------------------------------------------------------------
extern "C" void kernel_launch(void* const* d_in, const int* in_sizes, int n_in,
                              void* d_out, int out_size) {
    const float* x     = (const float*)d_in[0];
    const float* gamma = (const float*)d_in[1];
    const float* w_qkv = (const float*)d_in[2];
    const float* w_out = (const float*)d_in[3];
    float* out = (float*)d_out;

    __half *xh, *xl, *wqh, *wql, *woh, *qkh, *qkl, *vf, *aoh, *aol;
    cudaGetSymbolAddress((void**)&xh, g_xh);
    cudaGetSymbolAddress((void**)&xl, g_xl);
    cudaGetSymbolAddress((void**)&wqh, g_wqh);
    cudaGetSymbolAddress((void**)&wql, g_wql);
    cudaGetSymbolAddress((void**)&woh, g_woh);
    cudaGetSymbolAddress((void**)&qkh, g_qkh);
    cudaGetSymbolAddress((void**)&qkl, g_qkl);
    cudaGetSymbolAddress((void**)&vf, g_vf);
    cudaGetSymbolAddress((void**)&aoh, g_aoh);
    cudaGetSymbolAddress((void**)&aol, g_aol);

    cudaFuncSetAttribute(mma_gemm_kernel<true>,
                         cudaFuncAttributeMaxDynamicSharedMemorySize, GEMM_SMEM);
    cudaFuncSetAttribute(mma_gemm_kernel<false>,
                         cudaFuncAttributeMaxDynamicSharedMemorySize, GEMM_SMEM);
    cudaFuncSetAttribute(mma_attn_kernel,
                         cudaFuncAttributeMaxDynamicSharedMemorySize, ATT_SMEM);

    rms_split_x_kernel<<<N_TOK, 256>>>((const float4*)x, gamma);
    split_w_kernel<<<(DIM * QKV_N / 4) / 256, 256>>>((const float4*)w_qkv, wqh, wql);
    conv_w_kernel<<<(DINNER * DIM / 4) / 256, 256>>>((const float4*)w_out, woh);

    // qkv: q,k columns (n0 < 1024) use 3 products; v columns use 2.
    mma_gemm_kernel<true><<<dim3(QKV_N / 64, N_TOK / 128), 256, GEMM_SMEM>>>(
        xh, xl, wqh, wql, nullptr, qkh, qkl, vf, N_TOK, QKV_N, DIM, 2 * DINNER);

    mma_attn_kernel<<<dim3(64, 8), 128, ATT_SMEM>>>(qkh, qkl, vf, aoh, aol);

    // out-proj: 2 products everywhere (bl_col_limit = 0)
    mma_gemm_kernel<false><<<dim3(DIM / 64, N_TOK / 128), 256, GEMM_SMEM>>>(
        aoh, aol, woh, nullptr, out, nullptr, nullptr, nullptr, N_TOK, DIM, DINNER, 0);
}

// round 17
// speedup vs baseline: 1.2535x; 1.1369x over previous
#include <cuda_runtime.h>
#include <cuda_bf16.h>
#include <cuda_fp16.h>
#include <math.h>
#include <stdint.h>

#define N_TOK   4096
#define DIM     1024
#define HEADS   8
#define DHEAD   64
#define DINNER  512
#define QKV_N   1536

// Scratch (allocation-free rule: __device__ globals) — all fp16
__device__ __half g_xh[(size_t)N_TOK * DIM],   g_xl[(size_t)N_TOK * DIM];
__device__ __half g_wqh[(size_t)DIM * QKV_N],  g_wql[(size_t)DIM * QKV_N];
__device__ __half g_woh[(size_t)DINNER * DIM];                 // lo never needed (2-product)
__device__ __half g_qkh[(size_t)N_TOK * 1024], g_qkl[(size_t)N_TOK * 1024];
__device__ __half g_vf[(size_t)N_TOK * DINNER];
__device__ __half g_aoh[(size_t)N_TOK * DINNER], g_aol[(size_t)N_TOK * DINNER];

// ---------------------------------------------------------------------------
// Helpers
// ---------------------------------------------------------------------------
__device__ __forceinline__ void mma16816h(float* c,
    uint32_t a0, uint32_t a1, uint32_t a2, uint32_t a3,
    uint32_t b0, uint32_t b1) {
    asm volatile(
        "mma.sync.aligned.m16n8k16.row.col.f32.f16.f16.f32 "
        "{%0,%1,%2,%3}, {%4,%5,%6,%7}, {%8,%9}, {%0,%1,%2,%3};"
        : "+f"(c[0]), "+f"(c[1]), "+f"(c[2]), "+f"(c[3])
        : "r"(a0), "r"(a1), "r"(a2), "r"(a3), "r"(b0), "r"(b1));
}
__device__ __forceinline__ void ldsm4(uint32_t& r0, uint32_t& r1,
                                      uint32_t& r2, uint32_t& r3, const void* p) {
    uint32_t a = (uint32_t)__cvta_generic_to_shared(p);
    asm volatile("ldmatrix.sync.aligned.m8n8.x4.shared.b16 {%0,%1,%2,%3}, [%4];"
                 : "=r"(r0), "=r"(r1), "=r"(r2), "=r"(r3) : "r"(a));
}
__device__ __forceinline__ void ldsm4t(uint32_t& r0, uint32_t& r1,
                                       uint32_t& r2, uint32_t& r3, const void* p) {
    uint32_t a = (uint32_t)__cvta_generic_to_shared(p);
    asm volatile("ldmatrix.sync.aligned.m8n8.x4.trans.shared.b16 {%0,%1,%2,%3}, [%4];"
                 : "=r"(r0), "=r"(r1), "=r"(r2), "=r"(r3) : "r"(a));
}
// fp16 hi/lo split (~22-bit effective mantissa)
__device__ __forceinline__ void split2h(float v0, float v1,
                                        uint32_t& hi, uint32_t& lo) {
    __half h0 = __float2half_rn(v0);
    __half h1 = __float2half_rn(v1);
    __half l0 = __float2half_rn(v0 - __half2float(h0));
    __half l1 = __float2half_rn(v1 - __half2float(h1));
    __half2 hp; hp.x = h0; hp.y = h1;
    __half2 lp; lp.x = l0; lp.y = l1;
    hi = *(uint32_t*)&hp;
    lo = *(uint32_t*)&lp;
}
// packed fp16 2^t: {lo=2^t0, hi=2^t1}
__device__ __forceinline__ uint32_t exp2h2(float t0, float t1) {
    uint32_t r;
    asm("{\n\t.reg .b32 tmp;\n\t"
        "cvt.rn.f16x2.f32 tmp, %2, %1;\n\t"   // first src -> hi half
        "ex2.approx.f16x2 %0, tmp;\n\t}"
        : "=r"(r) : "f"(t0), "f"(t1));
    return r;
}
__device__ __forceinline__ void cp16(uint32_t d, const void* s) {
    asm volatile("cp.async.cg.shared.global [%0], [%1], 16;" :: "r"(d), "l"(s));
}
__device__ __forceinline__ void cpcommit() { asm volatile("cp.async.commit_group;" ::: "memory"); }
__device__ __forceinline__ void cpwait0()  { asm volatile("cp.async.wait_group 0;" ::: "memory"); }
__device__ __forceinline__ void cpwait1()  { asm volatile("cp.async.wait_group 1;" ::: "memory"); }

// ---------------------------------------------------------------------------
// Kernel 1: fused rmsnorm + gamma + fp16 hi/lo split of x.
// ---------------------------------------------------------------------------
__global__ __launch_bounds__(256)
void rms_split_x_kernel(const float4* __restrict__ x,
                        const float* __restrict__ gamma) {
    int row = blockIdx.x;
    float4 v = x[(size_t)row * 256 + threadIdx.x];
    float s = v.x * v.x + v.y * v.y + v.z * v.z + v.w * v.w;
    #pragma unroll
    for (int o = 16; o; o >>= 1) s += __shfl_xor_sync(0xffffffffu, s, o);
    __shared__ float ws[8];
    if ((threadIdx.x & 31) == 0) ws[threadIdx.x >> 5] = s;
    __syncthreads();
    float t = 0.f;
    #pragma unroll
    for (int i = 0; i < 8; i++) t += ws[i];
    float sc = 32.0f / fmaxf(sqrtf(t), 1e-12f);

    int col = threadIdx.x * 4;
    float4 gm = *(const float4*)(gamma + col);
    uint32_t h0, l0, h1, l1;
    split2h(v.x * sc * gm.x, v.y * sc * gm.y, h0, l0);
    split2h(v.z * sc * gm.z, v.w * sc * gm.w, h1, l1);
    size_t o4 = (size_t)row * DIM + col;
    *(uint2*)&g_xh[o4] = make_uint2(h0, h1);
    *(uint2*)&g_xl[o4] = make_uint2(l0, l1);
}

__global__ void split_w_kernel(const float4* __restrict__ w,
                               __half* __restrict__ hi,
                               __half* __restrict__ lo) {
    int i = blockIdx.x * 256 + threadIdx.x;
    float4 v = w[i];
    uint32_t h0, l0, h1, l1;
    split2h(v.x, v.y, h0, l0);
    split2h(v.z, v.w, h1, l1);
    *(uint2*)&hi[(size_t)4 * i] = make_uint2(h0, h1);
    *(uint2*)&lo[(size_t)4 * i] = make_uint2(l0, l1);
}
__global__ void conv_w_kernel(const float4* __restrict__ w,
                              __half* __restrict__ hi) {
    int i = blockIdx.x * 256 + threadIdx.x;
    float4 v = w[i];
    __half2 p0 = __floats2half2_rn(v.x, v.y);
    __half2 p1 = __floats2half2_rn(v.z, v.w);
    *(__half2*)&hi[(size_t)4 * i] = p0;
    *(__half2*)&hi[(size_t)4 * i + 2] = p1;
}

// ---------------------------------------------------------------------------
// fp16-split HMMA GEMM: C = (Ah+Al) @ B, 128x64 tile, BK=32, cp.async 2-stage,
// ldmatrix.x4. Products: ah*bh, al*bh always; ah*bl only if use_bl.
// ---------------------------------------------------------------------------
#define GA_ELE (128 * 40)
#define GB_ELE (32 * 72)
#define GSTAGE_ELE (2 * GA_ELE + 2 * GB_ELE)
#define GEMM_SMEM (2 * GSTAGE_ELE * 2)

template <bool QKV_OUT>
__global__ __launch_bounds__(256)
void mma_gemm_kernel(const __half* __restrict__ Ah,
                     const __half* __restrict__ Al,
                     const __half* __restrict__ Bh,
                     const __half* __restrict__ Bl,
                     float* __restrict__ C,
                     __half* __restrict__ Ch,
                     __half* __restrict__ Cl,
                     __half* __restrict__ Vf,
                     int M, int N, int K, int bl_col_limit) {
    extern __shared__ __align__(16) __half smg[];
    uint32_t smg_u = (uint32_t)__cvta_generic_to_shared(smg);
    int tid = threadIdx.x;
    int wid = tid >> 5, lane = tid & 31;
    int g = lane >> 2, t = lane & 3;
    int wm = wid & 3, wn = wid >> 2;
    int m0 = blockIdx.y * 128, n0 = blockIdx.x * 64;
    bool use_bl = (n0 < bl_col_limit);

    int arow = ((lane >> 3) & 1) * 8 + (lane & 7);
    int acol = (lane >> 4) * 8;
    int brow = lane & 15;
    int bcol = (lane >> 4) * 8;

    int a0r = tid >> 2,         a0k = (tid & 3) * 8;
    int a1r = (tid + 256) >> 2, a1k = ((tid + 256) & 3) * 8;
    int lbr = tid >> 3,         lbn = (tid & 7) * 8;

    #define G_LOAD(buf_, k0_) do {                                              \
        uint32_t sb = smg_u + (buf_) * (GSTAGE_ELE * 2);                        \
        cp16(sb + (a0r * 40 + a0k) * 2,                                         \
             Ah + (size_t)(m0 + a0r) * K + (k0_) + a0k);                        \
        cp16(sb + (a1r * 40 + a1k) * 2,                                         \
             Ah + (size_t)(m0 + a1r) * K + (k0_) + a1k);                        \
        cp16(sb + (GA_ELE + a0r * 40 + a0k) * 2,                                \
             Al + (size_t)(m0 + a0r) * K + (k0_) + a0k);                        \
        cp16(sb + (GA_ELE + a1r * 40 + a1k) * 2,                                \
             Al + (size_t)(m0 + a1r) * K + (k0_) + a1k);                        \
        cp16(sb + (2 * GA_ELE + lbr * 72 + lbn) * 2,                            \
             Bh + (size_t)((k0_) + lbr) * N + n0 + lbn);                        \
        if (use_bl)                                                             \
            cp16(sb + (2 * GA_ELE + GB_ELE + lbr * 72 + lbn) * 2,               \
                 Bl + (size_t)((k0_) + lbr) * N + n0 + lbn);                    \
        cpcommit();                                                             \
    } while (0)

    float c[2][4][4];
    #pragma unroll
    for (int mt = 0; mt < 2; mt++)
        #pragma unroll
        for (int nt = 0; nt < 4; nt++)
            #pragma unroll
            for (int e = 0; e < 4; e++) c[mt][nt][e] = 0.f;

    const int S = K / 32;
    G_LOAD(0, 0);
    for (int s = 0; s < S; s++) {
        if (s + 1 < S) { G_LOAD((s + 1) & 1, (s + 1) * 32); cpwait1(); }
        else           { cpwait0(); }
        __syncthreads();

        const __half* stg = smg + (s & 1) * GSTAGE_ELE;
        const __half* As0 = stg;
        const __half* As1 = stg + GA_ELE;
        const __half* Bs0 = stg + 2 * GA_ELE;
        const __half* Bs1 = stg + 2 * GA_ELE + GB_ELE;

        #pragma unroll
        for (int kk = 0; kk < 32; kk += 16) {
            uint32_t ah[2][4], al[2][4];
            #pragma unroll
            for (int mt = 0; mt < 2; mt++) {
                int r = wm * 32 + mt * 16;
                ldsm4(ah[mt][0], ah[mt][1], ah[mt][2], ah[mt][3],
                      &As0[(r + arow) * 40 + kk + acol]);
                ldsm4(al[mt][0], al[mt][1], al[mt][2], al[mt][3],
                      &As1[(r + arow) * 40 + kk + acol]);
            }
            #pragma unroll
            for (int p2 = 0; p2 < 2; p2++) {
                uint32_t bh0, bh1, bh2, bh3;
                ldsm4t(bh0, bh1, bh2, bh3,
                       &Bs0[(kk + brow) * 72 + wn * 32 + p2 * 16 + bcol]);
                mma16816h(c[0][2*p2],   ah[0][0], ah[0][1], ah[0][2], ah[0][3], bh0, bh1);
                mma16816h(c[0][2*p2+1], ah[0][0], ah[0][1], ah[0][2], ah[0][3], bh2, bh3);
                mma16816h(c[1][2*p2],   ah[1][0], ah[1][1], ah[1][2], ah[1][3], bh0, bh1);
                mma16816h(c[1][2*p2+1], ah[1][0], ah[1][1], ah[1][2], ah[1][3], bh2, bh3);
                mma16816h(c[0][2*p2],   al[0][0], al[0][1], al[0][2], al[0][3], bh0, bh1);
                mma16816h(c[0][2*p2+1], al[0][0], al[0][1], al[0][2], al[0][3], bh2, bh3);
                mma16816h(c[1][2*p2],   al[1][0], al[1][1], al[1][2], al[1][3], bh0, bh1);
                mma16816h(c[1][2*p2+1], al[1][0], al[1][1], al[1][2], al[1][3], bh2, bh3);
                if (use_bl) {
                    uint32_t bl0, bl1, bl2, bl3;
                    ldsm4t(bl0, bl1, bl2, bl3,
                           &Bs1[(kk + brow) * 72 + wn * 32 + p2 * 16 + bcol]);
                    mma16816h(c[0][2*p2],   ah[0][0], ah[0][1], ah[0][2], ah[0][3], bl0, bl1);
                    mma16816h(c[0][2*p2+1], ah[0][0], ah[0][1], ah[0][2], ah[0][3], bl2, bl3);
                    mma16816h(c[1][2*p2],   ah[1][0], ah[1][1], ah[1][2], ah[1][3], bl0, bl1);
                    mma16816h(c[1][2*p2+1], ah[1][0], ah[1][1], ah[1][2], ah[1][3], bl2, bl3);
                }
            }
        }
        __syncthreads();
    }

    #pragma unroll
    for (int mt = 0; mt < 2; mt++) {
        #pragma unroll
        for (int nt = 0; nt < 4; nt++) {
            int rowA = m0 + wm * 32 + mt * 16 + g;
            int col = n0 + wn * 32 + nt * 8 + 2 * t;
            if (QKV_OUT) {
                if (col < 2 * DINNER) {      // q,k: fp16 hi/lo pair
                    uint32_t hi, lo;
                    split2h(c[mt][nt][0], c[mt][nt][1], hi, lo);
                    *(uint32_t*)&Ch[(size_t)rowA * 1024 + col] = hi;
                    *(uint32_t*)&Cl[(size_t)rowA * 1024 + col] = lo;
                    split2h(c[mt][nt][2], c[mt][nt][3], hi, lo);
                    *(uint32_t*)&Ch[(size_t)(rowA + 8) * 1024 + col] = hi;
                    *(uint32_t*)&Cl[(size_t)(rowA + 8) * 1024 + col] = lo;
                } else {                     // v: single fp16
                    int vc = col - 2 * DINNER;
                    __half2 p0 = __floats2half2_rn(c[mt][nt][0], c[mt][nt][1]);
                    __half2 p1 = __floats2half2_rn(c[mt][nt][2], c[mt][nt][3]);
                    *(__half2*)&Vf[(size_t)rowA * DINNER + vc] = p0;
                    *(__half2*)&Vf[(size_t)(rowA + 8) * DINNER + vc] = p1;
                }
            } else {
                *(float2*)&C[(size_t)rowA * N + col] =
                    make_float2(c[mt][nt][0], c[mt][nt][1]);
                *(float2*)&C[(size_t)(rowA + 8) * N + col] =
                    make_float2(c[mt][nt][2], c[mt][nt][3]);
            }
        }
    }
    #undef G_LOAD
}

// ---------------------------------------------------------------------------
// Flash attention: S = 3-product fp16 (q,k hi/lo pairs); softmax computed
// DIRECTLY in fp16 via ex2.approx.f16x2 (half2 P == PV A-fragments);
// PV = 1 product (V single fp16). l = row sum (quad shfl-reduced) in fp32
// from the same rounded p (normalization self-consistent).
// ---------------------------------------------------------------------------
#define AT_ARR 4608
#define AT_STAGE (3 * AT_ARR)
#define ATT_SMEM (2 * AT_STAGE * 2)
#define L2E 1.4426950408889634f

__global__ __launch_bounds__(128)
void mma_attn_kernel(const __half* __restrict__ qkh,
                     const __half* __restrict__ qkl,
                     const __half* __restrict__ vf,
                     __half* __restrict__ aoh,
                     __half* __restrict__ aol) {
    extern __shared__ __align__(16) __half smb[];
    uint32_t smb_u = (uint32_t)__cvta_generic_to_shared(smb);

    int qt = 63 - blockIdx.x;          // heavy tiles first
    int h = blockIdx.y;
    int tid = threadIdx.x;
    int wid = tid >> 5, lane = tid & 31;
    int g = lane >> 2, t = lane & 3;
    int r0 = wid * 16;
    int gA = qt * 64 + r0 + g;

    int krow = ((lane >> 4) & 1) * 8 + (lane & 7);
    int kcol = ((lane >> 3) & 1) * 8;
    int vrow = lane & 15;
    int vcol = (lane >> 4) * 8;

    #define LOAD_KV(kt_, buf_) do {                                            \
        uint32_t sbase = smb_u + (buf_) * (AT_STAGE * 2);                      \
        _Pragma("unroll")                                                      \
        for (int j = 0; j < 4; j++) {                                          \
            int p = tid + j * 128;                                             \
            int rr = p >> 3, c8 = (p & 7) * 8;                                 \
            uint32_t dso = rr * 144 + c8 * 2;                                  \
            size_t bk = (size_t)((kt_) * 64 + rr) * 1024 + 512 + h * DHEAD + c8; \
            size_t bv = (size_t)((kt_) * 64 + rr) * DINNER + h * DHEAD + c8;   \
            cp16(sbase + dso,                  qkh + bk);                      \
            cp16(sbase + AT_ARR * 2 + dso,     qkl + bk);                      \
            cp16(sbase + 2 * AT_ARR * 2 + dso, vf + bv);                       \
        }                                                                      \
        cpcommit();                                                            \
    } while (0)

    uint32_t ahq[4][4], alq[4][4];
    {
        size_t rA = (size_t)gA * 1024 + h * DHEAD;
        size_t rB = (size_t)(gA + 8) * 1024 + h * DHEAD;
        #pragma unroll
        for (int d16 = 0; d16 < 4; d16++) {
            int cA = d16 * 16 + 2 * t, cB = d16 * 16 + 8 + 2 * t;
            ahq[d16][0] = *(const uint32_t*)&qkh[rA + cA];
            ahq[d16][1] = *(const uint32_t*)&qkh[rB + cA];
            ahq[d16][2] = *(const uint32_t*)&qkh[rA + cB];
            ahq[d16][3] = *(const uint32_t*)&qkh[rB + cB];
            alq[d16][0] = *(const uint32_t*)&qkl[rA + cA];
            alq[d16][1] = *(const uint32_t*)&qkl[rB + cA];
            alq[d16][2] = *(const uint32_t*)&qkl[rA + cB];
            alq[d16][3] = *(const uint32_t*)&qkl[rB + cB];
        }
    }

    float o[8][4];
    #pragma unroll
    for (int nt = 0; nt < 8; nt++)
        #pragma unroll
        for (int e = 0; e < 4; e++) o[nt][e] = 0.f;
    float m[2] = {-1e30f, -1e30f}, l[2] = {0.f, 0.f};

    LOAD_KV(0, 0);

    for (int kt = 0; kt <= qt; kt++) {
        __syncthreads();
        if (kt < qt) { LOAD_KV(kt + 1, (kt + 1) & 1); cpwait1(); }
        else         { cpwait0(); }
        __syncthreads();

        const __half* stg = smb + (kt & 1) * AT_STAGE;
        const __half* Kh = stg;
        const __half* Kl = stg + AT_ARR;
        const __half* Vs = stg + 2 * AT_ARR;

        float sc[8][4];
        #pragma unroll
        for (int nt = 0; nt < 8; nt++)
            #pragma unroll
            for (int e = 0; e < 4; e++) sc[nt][e] = 0.f;

        #pragma unroll
        for (int d16 = 0; d16 < 4; d16++) {
            #pragma unroll
            for (int p2 = 0; p2 < 4; p2++) {
                uint32_t bh0, bh1, bh2, bh3, bl0, bl1, bl2, bl3;
                ldsm4(bh0, bh1, bh2, bh3,
                      &Kh[(p2 * 16 + krow) * 72 + d16 * 16 + kcol]);
                ldsm4(bl0, bl1, bl2, bl3,
                      &Kl[(p2 * 16 + krow) * 72 + d16 * 16 + kcol]);
                mma16816h(sc[2*p2],   ahq[d16][0], ahq[d16][1], ahq[d16][2], ahq[d16][3], bh0, bh1);
                mma16816h(sc[2*p2+1], ahq[d16][0], ahq[d16][1], ahq[d16][2], ahq[d16][3], bh2, bh3);
                mma16816h(sc[2*p2],   ahq[d16][0], ahq[d16][1], ahq[d16][2], ahq[d16][3], bl0, bl1);
                mma16816h(sc[2*p2+1], ahq[d16][0], ahq[d16][1], ahq[d16][2], ahq[d16][3], bl2, bl3);
                mma16816h(sc[2*p2],   alq[d16][0], alq[d16][1], alq[d16][2], alq[d16][3], bh0, bh1);
                mma16816h(sc[2*p2+1], alq[d16][0], alq[d16][1], alq[d16][2], alq[d16][3], bh2, bh3);
            }
        }

        #pragma unroll
        for (int nt = 0; nt < 8; nt++)
            #pragma unroll
            for (int e = 0; e < 4; e++) sc[nt][e] *= 8.f;

        if (kt == qt) {
            #pragma unroll
            for (int nt = 0; nt < 8; nt++) {
                int colb = nt * 8 + 2 * t;
                int rA = r0 + g, rB = r0 + 8 + g;
                if (colb > rA)     sc[nt][0] = -1e30f;
                if (colb + 1 > rA) sc[nt][1] = -1e30f;
                if (colb > rB)     sc[nt][2] = -1e30f;
                if (colb + 1 > rB) sc[nt][3] = -1e30f;
            }
        }

        // fp16 softmax: p32[nt][hf] = half2{p(col 2t), p(col 2t+1)} for row hf
        uint32_t p32[8][2];
        #pragma unroll
        for (int hf = 0; hf < 2; hf++) {
            float mx = -1e30f;
            #pragma unroll
            for (int nt = 0; nt < 8; nt++) {
                mx = fmaxf(mx, sc[nt][2 * hf]);
                mx = fmaxf(mx, sc[nt][2 * hf + 1]);
            }
            mx = fmaxf(mx, __shfl_xor_sync(0xffffffffu, mx, 1));
            mx = fmaxf(mx, __shfl_xor_sync(0xffffffffu, mx, 2));
            float mnew = fmaxf(m[hf], mx);
            float corr = __expf(m[hf] - mnew);
            m[hf] = mnew;
            float mscale = mnew * L2E;
            float sum = 0.f;
            #pragma unroll
            for (int nt = 0; nt < 8; nt++) {
                uint32_t pp = exp2h2(sc[nt][2 * hf] * L2E - mscale,
                                     sc[nt][2 * hf + 1] * L2E - mscale);
                p32[nt][hf] = pp;
                __half2 hh = *(__half2*)&pp;
                float2 ff = __half22float2(hh);
                sum += ff.x + ff.y;
            }
            // FIX (R16 bug): l must be the ROW sum — reduce across the quad.
            sum += __shfl_xor_sync(0xffffffffu, sum, 1);
            sum += __shfl_xor_sync(0xffffffffu, sum, 2);
            l[hf] = l[hf] * corr + sum;
            #pragma unroll
            for (int nt = 0; nt < 8; nt++) {
                o[nt][2 * hf] *= corr;
                o[nt][2 * hf + 1] *= corr;
            }
        }

        // PV: 1 product; half2 p32 values ARE the A-fragments
        #pragma unroll
        for (int kk = 0; kk < 4; kk++) {
            #pragma unroll
            for (int p2 = 0; p2 < 4; p2++) {
                uint32_t v0, v1, v2, v3;
                ldsm4t(v0, v1, v2, v3,
                       &Vs[(kk * 16 + vrow) * 72 + p2 * 16 + vcol]);
                mma16816h(o[2*p2],   p32[2*kk][0], p32[2*kk][1],
                          p32[2*kk+1][0], p32[2*kk+1][1], v0, v1);
                mma16816h(o[2*p2+1], p32[2*kk][0], p32[2*kk][1],
                          p32[2*kk+1][0], p32[2*kk+1][1], v2, v3);
            }
        }
    }

    float inv0 = 1.f / l[0], inv1 = 1.f / l[1];
    #pragma unroll
    for (int nt = 0; nt < 8; nt++) {
        int col = h * DHEAD + nt * 8 + 2 * t;
        size_t rA = (size_t)gA * DINNER + col;
        size_t rB = (size_t)(gA + 8) * DINNER + col;
        uint32_t hi, lo;
        split2h(o[nt][0] * inv0, o[nt][1] * inv0, hi, lo);
        *(uint32_t*)&aoh[rA] = hi;
        *(uint32_t*)&aol[rA] = lo;
        split2h(o[nt][2] * inv1, o[nt][3] * inv1, hi, lo);
        *(uint32_t*)&aoh[rB] = hi;
        *(uint32_t*)&aol[rB] = lo;
    }
    #undef LOAD_KV
}

// ---------------------------------------------------------------------------
extern "C" void kernel_launch(void* const* d_in, const int* in_sizes, int n_in,
                              void* d_out, int out_size) {
    const float* x     = (const float*)d_in[0];
    const float* gamma = (const float*)d_in[1];
    const float* w_qkv = (const float*)d_in[2];
    const float* w_out = (const float*)d_in[3];
    float* out = (float*)d_out;

    __half *xh, *xl, *wqh, *wql, *woh, *qkh, *qkl, *vf, *aoh, *aol;
    cudaGetSymbolAddress((void**)&xh, g_xh);
    cudaGetSymbolAddress((void**)&xl, g_xl);
    cudaGetSymbolAddress((void**)&wqh, g_wqh);
    cudaGetSymbolAddress((void**)&wql, g_wql);
    cudaGetSymbolAddress((void**)&woh, g_woh);
    cudaGetSymbolAddress((void**)&qkh, g_qkh);
    cudaGetSymbolAddress((void**)&qkl, g_qkl);
    cudaGetSymbolAddress((void**)&vf, g_vf);
    cudaGetSymbolAddress((void**)&aoh, g_aoh);
    cudaGetSymbolAddress((void**)&aol, g_aol);

    cudaFuncSetAttribute(mma_gemm_kernel<true>,
                         cudaFuncAttributeMaxDynamicSharedMemorySize, GEMM_SMEM);
    cudaFuncSetAttribute(mma_gemm_kernel<false>,
                         cudaFuncAttributeMaxDynamicSharedMemorySize, GEMM_SMEM);
    cudaFuncSetAttribute(mma_attn_kernel,
                         cudaFuncAttributeMaxDynamicSharedMemorySize, ATT_SMEM);

    rms_split_x_kernel<<<N_TOK, 256>>>((const float4*)x, gamma);
    split_w_kernel<<<(DIM * QKV_N / 4) / 256, 256>>>((const float4*)w_qkv, wqh, wql);
    conv_w_kernel<<<(DINNER * DIM / 4) / 256, 256>>>((const float4*)w_out, woh);

    mma_gemm_kernel<true><<<dim3(QKV_N / 64, N_TOK / 128), 256, GEMM_SMEM>>>(
        xh, xl, wqh, wql, nullptr, qkh, qkl, vf, N_TOK, QKV_N, DIM, 2 * DINNER);

    mma_attn_kernel<<<dim3(64, 8), 128, ATT_SMEM>>>(qkh, qkl, vf, aoh, aol);

    mma_gemm_kernel<false><<<dim3(DIM / 64, N_TOK / 128), 256, GEMM_SMEM>>>(
        aoh, aol, woh, nullptr, out, nullptr, nullptr, nullptr, N_TOK, DIM, DINNER, 0);
}